// round 6
// baseline (speedup 1.0000x reference)
#include <cuda_runtime.h>
#include <cuda_bf16.h>
#include <cstdint>

#define INV_SQRT3 0.57735026918962576451f
#define INV_SQRT2 0.70710678118654752440f
#define LN_EPS 1e-5f

#define MAX_NODES 16384
#define MAX_EDGES 131072

// scratch (allocation-free rule: __device__ globals)
__device__ int g_hist[MAX_NODES];
__device__ int g_rank[MAX_EDGES];
__device__ int g_start[MAX_NODES + 1];
__device__ int g_sorted[MAX_EDGES];

__device__ __forceinline__ float warp_sum(float v) {
    v += __shfl_xor_sync(0xffffffffu, v, 16);
    v += __shfl_xor_sync(0xffffffffu, v, 8);
    v += __shfl_xor_sync(0xffffffffu, v, 4);
    v += __shfl_xor_sync(0xffffffffu, v, 2);
    v += __shfl_xor_sync(0xffffffffu, v, 1);
    return v;
}

// ---------------------------------------------------------------------------
// Sort pipeline: counting sort of edge ids by edge_dst (rank-based)
// ---------------------------------------------------------------------------
__global__ void hist_zero_kernel(int n_nodes) {
    int i = blockIdx.x * blockDim.x + threadIdx.x;
    if (i < n_nodes) g_hist[i] = 0;
}

__global__ void hist_count_kernel(const int* __restrict__ edge_dst, int n_edges) {
    int i4 = (blockIdx.x * blockDim.x + threadIdx.x) * 4;
    if (i4 + 3 < n_edges) {
        const int4 d = *reinterpret_cast<const int4*>(edge_dst + i4);
        g_rank[i4 + 0] = atomicAdd(&g_hist[d.x], 1);
        g_rank[i4 + 1] = atomicAdd(&g_hist[d.y], 1);
        g_rank[i4 + 2] = atomicAdd(&g_hist[d.z], 1);
        g_rank[i4 + 3] = atomicAdd(&g_hist[d.w], 1);
    } else {
        for (int i = i4; i < n_edges; i++)
            g_rank[i] = atomicAdd(&g_hist[edge_dst[i]], 1);
    }
}

// single block, 1024 threads, 16 bins per thread (covers 16384 nodes)
__global__ void __launch_bounds__(1024) scan_kernel(int n_nodes) {
    __shared__ int ssum[1024];
    const int t = threadIdx.x;
    const int base = t * 16;

    int v[16];
    int s = 0;
#pragma unroll
    for (int i = 0; i < 16; i++) {
        int idx = base + i;
        v[i] = (idx < n_nodes) ? g_hist[idx] : 0;
        s += v[i];
    }
    ssum[t] = s;
    __syncthreads();

    for (int off = 1; off < 1024; off <<= 1) {
        int x = (t >= off) ? ssum[t - off] : 0;
        __syncthreads();
        ssum[t] += x;
        __syncthreads();
    }

    int run = (t == 0) ? 0 : ssum[t - 1];  // exclusive base
#pragma unroll
    for (int i = 0; i < 16; i++) {
        int idx = base + i;
        if (idx < n_nodes) g_start[idx] = run;
        run += v[i];
    }
    if (t == 1023) g_start[n_nodes] = run;
}

__global__ void scatter_kernel(const int* __restrict__ edge_dst, int n_edges) {
    int i4 = (blockIdx.x * blockDim.x + threadIdx.x) * 4;
    if (i4 + 3 < n_edges) {
        const int4 d = *reinterpret_cast<const int4*>(edge_dst + i4);
        const int4 r = *reinterpret_cast<const int4*>(g_rank + i4);
        g_sorted[__ldg(g_start + d.x) + r.x] = i4 + 0;
        g_sorted[__ldg(g_start + d.y) + r.y] = i4 + 1;
        g_sorted[__ldg(g_start + d.z) + r.z] = i4 + 2;
        g_sorted[__ldg(g_start + d.w) + r.w] = i4 + 3;
    } else {
        for (int i = i4; i < n_edges; i++)
            g_sorted[g_start[edge_dst[i]] + g_rank[i]] = i;
    }
}

// ---------------------------------------------------------------------------
// Per-edge loaded operands + accumulation helpers
// ---------------------------------------------------------------------------
struct EdgeAcc {
    float v[30];
    // 0-3: out0a, 4-5: out0b, 6-17: out1a(A), 18-23: out1b(B), 24-29: out1c(C)
};

struct EdgeData {
    float4 sh;
    float4 xs, w0, w1;
    float2 w2, w3, w4, p0, p1, p2;

    __device__ __forceinline__ void load(const float* __restrict__ node_feat,
                                         const float* __restrict__ edge_sh,
                                         const float* __restrict__ edge_weight,
                                         int e, int s, int lane) {
        sh = __ldg(reinterpret_cast<const float4*>(edge_sh) + e);
        const float* xrow = node_feat + (size_t)s * 320u;
        const float* wrow = edge_weight + (size_t)e * 448u;
        xs = __ldg(reinterpret_cast<const float4*>(xrow + 4 * lane));
        w0 = __ldg(reinterpret_cast<const float4*>(wrow + 4 * lane));
        w1 = __ldg(reinterpret_cast<const float4*>(wrow + 128 + 4 * lane));
        w2 = __ldg(reinterpret_cast<const float2*>(wrow + 256 + 2 * lane));
        w3 = __ldg(reinterpret_cast<const float2*>(wrow + 320 + 2 * lane));
        w4 = __ldg(reinterpret_cast<const float2*>(wrow + 384 + 2 * lane));
        p0 = __ldg(reinterpret_cast<const float2*>(xrow + 128 + 6 * lane));
        p1 = __ldg(reinterpret_cast<const float2*>(xrow + 128 + 6 * lane + 2));
        p2 = __ldg(reinterpret_cast<const float2*>(xrow + 128 + 6 * lane + 4));
    }

    __device__ __forceinline__ void accum(EdgeAcc& ac) const {
        const float ys = sh.x, yv0 = sh.y, yv1 = sh.z, yv2 = sh.w;

        ac.v[0] += w0.x * xs.x * ys;
        ac.v[1] += w0.y * xs.y * ys;
        ac.v[2] += w0.z * xs.z * ys;
        ac.v[3] += w0.w * xs.w * ys;

        const float t0 = w1.x * xs.x, t1 = w1.y * xs.y;
        const float t2 = w1.z * xs.z, t3 = w1.w * xs.w;
        ac.v[6]  += t0 * yv0; ac.v[7]  += t0 * yv1; ac.v[8]  += t0 * yv2;
        ac.v[9]  += t1 * yv0; ac.v[10] += t1 * yv1; ac.v[11] += t1 * yv2;
        ac.v[12] += t2 * yv0; ac.v[13] += t2 * yv1; ac.v[14] += t2 * yv2;
        ac.v[15] += t3 * yv0; ac.v[16] += t3 * yv1; ac.v[17] += t3 * yv2;

        // xv[v0] = (p0.x, p0.y, p1.x) ; xv[v1] = (p1.y, p2.x, p2.y)
        const float d0 = p0.x * yv0 + p0.y * yv1 + p1.x * yv2;
        const float d1 = p1.y * yv0 + p2.x * yv1 + p2.y * yv2;
        ac.v[4] += w3.x * d0 * INV_SQRT3;
        ac.v[5] += w3.y * d1 * INV_SQRT3;

        const float c0 = w2.x * ys, c1 = w2.y * ys;
        ac.v[18] += c0 * p0.x; ac.v[19] += c0 * p0.y; ac.v[20] += c0 * p1.x;
        ac.v[21] += c1 * p1.y; ac.v[22] += c1 * p2.x; ac.v[23] += c1 * p2.y;

        const float k0 = w4.x * INV_SQRT2, k1 = w4.y * INV_SQRT2;
        ac.v[24] += k0 * (p0.y * yv2 - p1.x * yv1);
        ac.v[25] += k0 * (p1.x * yv0 - p0.x * yv2);
        ac.v[26] += k0 * (p0.x * yv1 - p0.y * yv0);
        ac.v[27] += k1 * (p2.x * yv2 - p2.y * yv1);
        ac.v[28] += k1 * (p2.y * yv0 - p1.y * yv2);
        ac.v[29] += k1 * (p1.y * yv1 - p2.x * yv0);
    }
};

// ---------------------------------------------------------------------------
// Fused gather + depthwise TP + bias + equivariant LN.
// TWO warps per node (each half the edge range, 2-edge unroll inside),
// combined through shared memory; even warp does bias+LN+store.
// Block = 256 threads = 8 warps = 4 nodes.
// ---------------------------------------------------------------------------
__global__ void __launch_bounds__(256, 2) fused_tp_ln_kernel(
    const float* __restrict__ node_feat,   // (N, 320)
    const float* __restrict__ edge_sh,     // (E, 4)
    const float* __restrict__ edge_weight, // (E, 448)
    const float* __restrict__ tp_bias,     // (192,)
    const int*   __restrict__ edge_src,
    const float* __restrict__ lnw,         // (448,)
    const float* __restrict__ lnb,         // (192,)
    float*       __restrict__ out,         // (N, 960)
    int n_nodes)
{
    __shared__ float sacc[4][960];

    const int warp = threadIdx.x >> 5;       // 0..7
    const int lane = threadIdx.x & 31;
    const int nodeLocal = warp >> 1;          // 0..3
    const int sub = warp & 1;                 // 0 or 1
    const int node = blockIdx.x * 4 + nodeLocal;
    const bool valid = (node < n_nodes);

    int beg = 0, end = 0;
    if (valid) {
        beg = g_start[node];
        end = g_start[node + 1];
    }
    const int deg = end - beg;
    const int mid = beg + ((deg + 1) >> 1);

    // this warp's half of the edge range
    const int my_beg = sub ? mid : beg;
    const int my_end = sub ? end : mid;

    EdgeAcc ac;
#pragma unroll
    for (int i = 0; i < 30; i++) ac.v[i] = 0.f;

    int ei = my_beg;
    for (; ei + 1 < my_end; ei += 2) {
        const int e0 = __ldg(g_sorted + ei);
        const int e1 = __ldg(g_sorted + ei + 1);
        const int s0 = __ldg(edge_src + e0);
        const int s1 = __ldg(edge_src + e1);
        EdgeData d0, d1;
        d0.load(node_feat, edge_sh, edge_weight, e0, s0, lane);
        d1.load(node_feat, edge_sh, edge_weight, e1, s1, lane);
        d0.accum(ac);
        d1.accum(ac);
    }
    if (ei < my_end) {
        const int e0 = __ldg(g_sorted + ei);
        const int s0 = __ldg(edge_src + e0);
        EdgeData d0;
        d0.load(node_feat, edge_sh, edge_weight, e0, s0, lane);
        d0.accum(ac);
    }

    // odd warp publishes partials; even warp combines
    if (sub == 1) {
        float* dst = &sacc[nodeLocal][lane * 30];
#pragma unroll
        for (int i = 0; i < 30; i++) dst[i] = ac.v[i];
    }
    __syncthreads();
    if (sub == 1 || !valid) return;

    {
        const float* src = &sacc[nodeLocal][lane * 30];
#pragma unroll
        for (int i = 0; i < 30; i++) ac.v[i] += src[i];
    }

    // per-edge bias, summed over deg edges
    const float fdeg = (float)deg;
    {
        const float4 b0 = __ldg(reinterpret_cast<const float4*>(tp_bias + 4 * lane));
        ac.v[0] += fdeg * b0.x; ac.v[1] += fdeg * b0.y;
        ac.v[2] += fdeg * b0.z; ac.v[3] += fdeg * b0.w;
        const float2 bb = __ldg(reinterpret_cast<const float2*>(tp_bias + 128 + 2 * lane));
        ac.v[4] += fdeg * bb.x; ac.v[5] += fdeg * bb.y;
    }

    // ---- equivariant LayerNorm on register-resident row ---------------------
    float s0 = ac.v[0] + ac.v[1] + ac.v[2] + ac.v[3];
    float q0 = ac.v[0]*ac.v[0] + ac.v[1]*ac.v[1] + ac.v[2]*ac.v[2] + ac.v[3]*ac.v[3];
    float s1 = ac.v[4] + ac.v[5];
    float q1 = ac.v[4]*ac.v[4] + ac.v[5]*ac.v[5];
    float q2 = 0.f, q3 = 0.f, q4 = 0.f;
#pragma unroll
    for (int i = 6; i < 18; i++) q2 += ac.v[i] * ac.v[i];
#pragma unroll
    for (int i = 18; i < 24; i++) q3 += ac.v[i] * ac.v[i];
#pragma unroll
    for (int i = 24; i < 30; i++) q4 += ac.v[i] * ac.v[i];

    s0 = warp_sum(s0); q0 = warp_sum(q0);
    s1 = warp_sum(s1); q1 = warp_sum(q1);
    q2 = warp_sum(q2); q3 = warp_sum(q3); q4 = warp_sum(q4);

    const float mu0 = s0 * (1.f / 128.f);
    const float r0  = rsqrtf(fmaxf(q0 * (1.f / 128.f) - mu0 * mu0, 0.f) + LN_EPS);
    const float mu1 = s1 * (1.f / 64.f);
    const float r1  = rsqrtf(fmaxf(q1 * (1.f / 64.f) - mu1 * mu1, 0.f) + LN_EPS);
    const float r2  = rsqrtf(q2 * (1.f / 384.f) + LN_EPS);
    const float r3  = rsqrtf(q3 * (1.f / 192.f) + LN_EPS);
    const float r4  = rsqrtf(q4 * (1.f / 192.f) + LN_EPS);

    float* row = out + (size_t)node * 960u;

    {   // field0
        const float4 wv = __ldg(reinterpret_cast<const float4*>(lnw + 4 * lane));
        const float4 bv = __ldg(reinterpret_cast<const float4*>(lnb + 4 * lane));
        float4 o;
        o.x = (ac.v[0] - mu0) * r0 * wv.x + bv.x;
        o.y = (ac.v[1] - mu0) * r0 * wv.y + bv.y;
        o.z = (ac.v[2] - mu0) * r0 * wv.z + bv.z;
        o.w = (ac.v[3] - mu0) * r0 * wv.w + bv.w;
        *reinterpret_cast<float4*>(row + 4 * lane) = o;
    }
    {   // field1
        const float2 wv = __ldg(reinterpret_cast<const float2*>(lnw + 128 + 2 * lane));
        const float2 bv = __ldg(reinterpret_cast<const float2*>(lnb + 128 + 2 * lane));
        float2 o;
        o.x = (ac.v[4] - mu1) * r1 * wv.x + bv.x;
        o.y = (ac.v[5] - mu1) * r1 * wv.y + bv.y;
        *reinterpret_cast<float2*>(row + 128 + 2 * lane) = o;
    }
    {   // field2: channels u = 4*lane + {0..3}
        const float4 wv = __ldg(reinterpret_cast<const float4*>(lnw + 192 + 4 * lane));
        const float sa = wv.x * r2, sb = wv.y * r2, sc = wv.z * r2, sd = wv.w * r2;
        float4 o1 = make_float4(ac.v[6]  * sa, ac.v[7]  * sa, ac.v[8]  * sa, ac.v[9]  * sb);
        float4 o2 = make_float4(ac.v[10] * sb, ac.v[11] * sb, ac.v[12] * sc, ac.v[13] * sc);
        float4 o3 = make_float4(ac.v[14] * sc, ac.v[15] * sd, ac.v[16] * sd, ac.v[17] * sd);
        *reinterpret_cast<float4*>(row + 192 + 12 * lane)     = o1;
        *reinterpret_cast<float4*>(row + 192 + 12 * lane + 4) = o2;
        *reinterpret_cast<float4*>(row + 192 + 12 * lane + 8) = o3;
    }
    {   // field3
        const float2 wv = __ldg(reinterpret_cast<const float2*>(lnw + 320 + 2 * lane));
        const float sa = wv.x * r3, sb = wv.y * r3;
        *reinterpret_cast<float2*>(row + 576 + 6 * lane)     = make_float2(ac.v[18] * sa, ac.v[19] * sa);
        *reinterpret_cast<float2*>(row + 576 + 6 * lane + 2) = make_float2(ac.v[20] * sa, ac.v[21] * sb);
        *reinterpret_cast<float2*>(row + 576 + 6 * lane + 4) = make_float2(ac.v[22] * sb, ac.v[23] * sb);
    }
    {   // field4
        const float2 wv = __ldg(reinterpret_cast<const float2*>(lnw + 384 + 2 * lane));
        const float sa = wv.x * r4, sb = wv.y * r4;
        *reinterpret_cast<float2*>(row + 768 + 6 * lane)     = make_float2(ac.v[24] * sa, ac.v[25] * sa);
        *reinterpret_cast<float2*>(row + 768 + 6 * lane + 2) = make_float2(ac.v[26] * sa, ac.v[27] * sb);
        *reinterpret_cast<float2*>(row + 768 + 6 * lane + 4) = make_float2(ac.v[28] * sb, ac.v[29] * sb);
    }
}

// ---------------------------------------------------------------------------
extern "C" void kernel_launch(void* const* d_in, const int* in_sizes, int n_in,
                              void* d_out, int out_size)
{
    const float* node_feat   = (const float*)d_in[0];
    const float* edge_sh     = (const float*)d_in[1];
    const float* edge_weight = (const float*)d_in[2];
    const float* tp_bias     = (const float*)d_in[3];
    const float* ln_weight   = (const float*)d_in[4];
    const float* ln_bias     = (const float*)d_in[5];
    const int*   edge_src    = (const int*)d_in[6];
    const int*   edge_dst    = (const int*)d_in[7];
    float* out = (float*)d_out;

    const int n_nodes = in_sizes[0] / 320;
    const int n_edges = in_sizes[7];

    hist_zero_kernel<<<(n_nodes + 255) / 256, 256>>>(n_nodes);
    {
        const int threads = (n_edges + 3) / 4;
        hist_count_kernel<<<(threads + 255) / 256, 256>>>(edge_dst, n_edges);
    }
    scan_kernel<<<1, 1024>>>(n_nodes);
    {
        const int threads = (n_edges + 3) / 4;
        scatter_kernel<<<(threads + 255) / 256, 256>>>(edge_dst, n_edges);
    }

    // 2 warps per node, 4 nodes per 256-thread block
    const int blocks = (n_nodes + 3) / 4;
    fused_tp_ln_kernel<<<blocks, 256>>>(node_feat, edge_sh, edge_weight,
                                        tp_bias, edge_src, ln_weight, ln_bias,
                                        out, n_nodes);
}

// round 7
// speedup vs baseline: 1.1946x; 1.1946x over previous
#include <cuda_runtime.h>
#include <cuda_bf16.h>
#include <cstdint>

#define INV_SQRT3 0.57735026918962576451f
#define INV_SQRT2 0.70710678118654752440f
#define LN_EPS 1e-5f

#define MAX_NODES 16384
#define MAX_EDGES 131072

// scratch (allocation-free rule: __device__ globals; statically zero-initialized)
__device__ int  g_hist[MAX_NODES];          // ALWAYS zero at kernel_launch entry
__device__ int  g_rank[MAX_EDGES];
__device__ int  g_start[MAX_NODES + 1];
__device__ int2 g_sorted2[MAX_EDGES];       // (edge_id, src_node)

__device__ __forceinline__ float warp_sum(float v) {
    v += __shfl_xor_sync(0xffffffffu, v, 16);
    v += __shfl_xor_sync(0xffffffffu, v, 8);
    v += __shfl_xor_sync(0xffffffffu, v, 4);
    v += __shfl_xor_sync(0xffffffffu, v, 2);
    v += __shfl_xor_sync(0xffffffffu, v, 1);
    return v;
}

// ---------------------------------------------------------------------------
// Sort pipeline: counting sort of edge ids by edge_dst (rank-based).
// g_hist is zero on entry (static init on first call, re-zeroed by
// scatter_kernel at the end of every call) -- no separate zero kernel.
// ---------------------------------------------------------------------------
__global__ void hist_count_kernel(const int* __restrict__ edge_dst, int n_edges) {
    int i4 = (blockIdx.x * blockDim.x + threadIdx.x) * 4;
    if (i4 + 3 < n_edges) {
        const int4 d = *reinterpret_cast<const int4*>(edge_dst + i4);
        g_rank[i4 + 0] = atomicAdd(&g_hist[d.x], 1);
        g_rank[i4 + 1] = atomicAdd(&g_hist[d.y], 1);
        g_rank[i4 + 2] = atomicAdd(&g_hist[d.z], 1);
        g_rank[i4 + 3] = atomicAdd(&g_hist[d.w], 1);
    } else {
        for (int i = i4; i < n_edges; i++)
            g_rank[i] = atomicAdd(&g_hist[edge_dst[i]], 1);
    }
}

// single block, 1024 threads, 16 bins per thread (covers 16384 nodes)
__global__ void __launch_bounds__(1024) scan_kernel(int n_nodes) {
    __shared__ int ssum[1024];
    const int t = threadIdx.x;
    const int base = t * 16;

    int v[16];
    int s = 0;
#pragma unroll
    for (int i = 0; i < 16; i++) {
        int idx = base + i;
        v[i] = (idx < n_nodes) ? g_hist[idx] : 0;
        s += v[i];
    }
    ssum[t] = s;
    __syncthreads();

    for (int off = 1; off < 1024; off <<= 1) {
        int x = (t >= off) ? ssum[t - off] : 0;
        __syncthreads();
        ssum[t] += x;
        __syncthreads();
    }

    int run = (t == 0) ? 0 : ssum[t - 1];  // exclusive base
#pragma unroll
    for (int i = 0; i < 16; i++) {
        int idx = base + i;
        if (idx < n_nodes) g_start[idx] = run;
        run += v[i];
    }
    if (t == 1023) g_start[n_nodes] = run;
}

// atomic-free scatter using precomputed rank; stores (edge, src) pairs.
// Also restores g_hist to zero for the next kernel_launch call.
__global__ void scatter_kernel(const int* __restrict__ edge_dst,
                               const int* __restrict__ edge_src,
                               int n_edges, int n_nodes) {
    const int tid = blockIdx.x * blockDim.x + threadIdx.x;
    int i4 = tid * 4;
    if (i4 + 3 < n_edges) {
        const int4 d = *reinterpret_cast<const int4*>(edge_dst + i4);
        const int4 r = *reinterpret_cast<const int4*>(g_rank + i4);
        const int4 s = *reinterpret_cast<const int4*>(edge_src + i4);
        g_sorted2[__ldg(g_start + d.x) + r.x] = make_int2(i4 + 0, s.x);
        g_sorted2[__ldg(g_start + d.y) + r.y] = make_int2(i4 + 1, s.y);
        g_sorted2[__ldg(g_start + d.z) + r.z] = make_int2(i4 + 2, s.z);
        g_sorted2[__ldg(g_start + d.w) + r.w] = make_int2(i4 + 3, s.w);
    } else {
        for (int i = i4; i < n_edges; i++)
            g_sorted2[g_start[edge_dst[i]] + g_rank[i]] = make_int2(i, edge_src[i]);
    }
    // restore invariant: g_hist == 0 at next call's entry
    if (tid < n_nodes) g_hist[tid] = 0;
}

// ---------------------------------------------------------------------------
// Per-edge loaded operands + accumulation helpers
// ---------------------------------------------------------------------------
struct EdgeAcc {
    float v[30];
    // 0-3: out0a, 4-5: out0b, 6-17: out1a(A), 18-23: out1b(B), 24-29: out1c(C)
};

struct EdgeData {
    float4 sh;
    float4 xs, w0, w1;
    float2 w2, w3, w4, p0, p1, p2;

    __device__ __forceinline__ void load(const float* __restrict__ node_feat,
                                         const float* __restrict__ edge_sh,
                                         const float* __restrict__ edge_weight,
                                         int e, int s, int lane) {
        sh = __ldg(reinterpret_cast<const float4*>(edge_sh) + e);
        const float* xrow = node_feat + (size_t)s * 320u;
        const float* wrow = edge_weight + (size_t)e * 448u;
        xs = __ldg(reinterpret_cast<const float4*>(xrow + 4 * lane));
        w0 = __ldg(reinterpret_cast<const float4*>(wrow + 4 * lane));
        w1 = __ldg(reinterpret_cast<const float4*>(wrow + 128 + 4 * lane));
        w2 = __ldg(reinterpret_cast<const float2*>(wrow + 256 + 2 * lane));
        w3 = __ldg(reinterpret_cast<const float2*>(wrow + 320 + 2 * lane));
        w4 = __ldg(reinterpret_cast<const float2*>(wrow + 384 + 2 * lane));
        p0 = __ldg(reinterpret_cast<const float2*>(xrow + 128 + 6 * lane));
        p1 = __ldg(reinterpret_cast<const float2*>(xrow + 128 + 6 * lane + 2));
        p2 = __ldg(reinterpret_cast<const float2*>(xrow + 128 + 6 * lane + 4));
    }

    __device__ __forceinline__ void accum(EdgeAcc& ac) const {
        const float ys = sh.x, yv0 = sh.y, yv1 = sh.z, yv2 = sh.w;

        ac.v[0] += w0.x * xs.x * ys;
        ac.v[1] += w0.y * xs.y * ys;
        ac.v[2] += w0.z * xs.z * ys;
        ac.v[3] += w0.w * xs.w * ys;

        const float t0 = w1.x * xs.x, t1 = w1.y * xs.y;
        const float t2 = w1.z * xs.z, t3 = w1.w * xs.w;
        ac.v[6]  += t0 * yv0; ac.v[7]  += t0 * yv1; ac.v[8]  += t0 * yv2;
        ac.v[9]  += t1 * yv0; ac.v[10] += t1 * yv1; ac.v[11] += t1 * yv2;
        ac.v[12] += t2 * yv0; ac.v[13] += t2 * yv1; ac.v[14] += t2 * yv2;
        ac.v[15] += t3 * yv0; ac.v[16] += t3 * yv1; ac.v[17] += t3 * yv2;

        // xv[v0] = (p0.x, p0.y, p1.x) ; xv[v1] = (p1.y, p2.x, p2.y)
        const float d0 = p0.x * yv0 + p0.y * yv1 + p1.x * yv2;
        const float d1 = p1.y * yv0 + p2.x * yv1 + p2.y * yv2;
        ac.v[4] += w3.x * d0 * INV_SQRT3;
        ac.v[5] += w3.y * d1 * INV_SQRT3;

        const float c0 = w2.x * ys, c1 = w2.y * ys;
        ac.v[18] += c0 * p0.x; ac.v[19] += c0 * p0.y; ac.v[20] += c0 * p1.x;
        ac.v[21] += c1 * p1.y; ac.v[22] += c1 * p2.x; ac.v[23] += c1 * p2.y;

        const float k0 = w4.x * INV_SQRT2, k1 = w4.y * INV_SQRT2;
        ac.v[24] += k0 * (p0.y * yv2 - p1.x * yv1);
        ac.v[25] += k0 * (p1.x * yv0 - p0.x * yv2);
        ac.v[26] += k0 * (p0.x * yv1 - p0.y * yv0);
        ac.v[27] += k1 * (p2.x * yv2 - p2.y * yv1);
        ac.v[28] += k1 * (p2.y * yv0 - p1.y * yv2);
        ac.v[29] += k1 * (p1.y * yv1 - p2.x * yv0);
    }
};

// ---------------------------------------------------------------------------
// Fused gather + depthwise TP + bias + equivariant LN. One warp per node,
// 2-edge unroll; index chain depth is 2 (sorted (e,src) pair -> bulk loads).
// ---------------------------------------------------------------------------
__global__ void __launch_bounds__(256, 2) fused_tp_ln_kernel(
    const float* __restrict__ node_feat,   // (N, 320)
    const float* __restrict__ edge_sh,     // (E, 4)
    const float* __restrict__ edge_weight, // (E, 448)
    const float* __restrict__ tp_bias,     // (192,)
    const float* __restrict__ lnw,         // (448,)
    const float* __restrict__ lnb,         // (192,)
    float*       __restrict__ out,         // (N, 960)
    int n_nodes)
{
    const int warp = (blockIdx.x * blockDim.x + threadIdx.x) >> 5;
    const int lane = threadIdx.x & 31;
    if (warp >= n_nodes) return;
    const int node = warp;

    const int beg = g_start[node];
    const int end = g_start[node + 1];
    const int deg = end - beg;

    EdgeAcc ac;
#pragma unroll
    for (int i = 0; i < 30; i++) ac.v[i] = 0.f;

    int ei = beg;
    for (; ei + 1 < end; ei += 2) {
        const int2 es0 = __ldg(g_sorted2 + ei);
        const int2 es1 = __ldg(g_sorted2 + ei + 1);
        EdgeData d0, d1;
        d0.load(node_feat, edge_sh, edge_weight, es0.x, es0.y, lane);
        d1.load(node_feat, edge_sh, edge_weight, es1.x, es1.y, lane);
        d0.accum(ac);
        d1.accum(ac);
    }
    if (ei < end) {
        const int2 es0 = __ldg(g_sorted2 + ei);
        EdgeData d0;
        d0.load(node_feat, edge_sh, edge_weight, es0.x, es0.y, lane);
        d0.accum(ac);
    }

    // per-edge bias, summed over deg edges
    const float fdeg = (float)deg;
    {
        const float4 b0 = __ldg(reinterpret_cast<const float4*>(tp_bias + 4 * lane));
        ac.v[0] += fdeg * b0.x; ac.v[1] += fdeg * b0.y;
        ac.v[2] += fdeg * b0.z; ac.v[3] += fdeg * b0.w;
        const float2 bb = __ldg(reinterpret_cast<const float2*>(tp_bias + 128 + 2 * lane));
        ac.v[4] += fdeg * bb.x; ac.v[5] += fdeg * bb.y;
    }

    // ---- equivariant LayerNorm on register-resident row ---------------------
    float s0 = ac.v[0] + ac.v[1] + ac.v[2] + ac.v[3];
    float q0 = ac.v[0]*ac.v[0] + ac.v[1]*ac.v[1] + ac.v[2]*ac.v[2] + ac.v[3]*ac.v[3];
    float s1 = ac.v[4] + ac.v[5];
    float q1 = ac.v[4]*ac.v[4] + ac.v[5]*ac.v[5];
    float q2 = 0.f, q3 = 0.f, q4 = 0.f;
#pragma unroll
    for (int i = 6; i < 18; i++) q2 += ac.v[i] * ac.v[i];
#pragma unroll
    for (int i = 18; i < 24; i++) q3 += ac.v[i] * ac.v[i];
#pragma unroll
    for (int i = 24; i < 30; i++) q4 += ac.v[i] * ac.v[i];

    s0 = warp_sum(s0); q0 = warp_sum(q0);
    s1 = warp_sum(s1); q1 = warp_sum(q1);
    q2 = warp_sum(q2); q3 = warp_sum(q3); q4 = warp_sum(q4);

    const float mu0 = s0 * (1.f / 128.f);
    const float r0  = rsqrtf(fmaxf(q0 * (1.f / 128.f) - mu0 * mu0, 0.f) + LN_EPS);
    const float mu1 = s1 * (1.f / 64.f);
    const float r1  = rsqrtf(fmaxf(q1 * (1.f / 64.f) - mu1 * mu1, 0.f) + LN_EPS);
    const float r2  = rsqrtf(q2 * (1.f / 384.f) + LN_EPS);
    const float r3  = rsqrtf(q3 * (1.f / 192.f) + LN_EPS);
    const float r4  = rsqrtf(q4 * (1.f / 192.f) + LN_EPS);

    float* row = out + (size_t)node * 960u;

    {   // field0
        const float4 wv = __ldg(reinterpret_cast<const float4*>(lnw + 4 * lane));
        const float4 bv = __ldg(reinterpret_cast<const float4*>(lnb + 4 * lane));
        float4 o;
        o.x = (ac.v[0] - mu0) * r0 * wv.x + bv.x;
        o.y = (ac.v[1] - mu0) * r0 * wv.y + bv.y;
        o.z = (ac.v[2] - mu0) * r0 * wv.z + bv.z;
        o.w = (ac.v[3] - mu0) * r0 * wv.w + bv.w;
        *reinterpret_cast<float4*>(row + 4 * lane) = o;
    }
    {   // field1
        const float2 wv = __ldg(reinterpret_cast<const float2*>(lnw + 128 + 2 * lane));
        const float2 bv = __ldg(reinterpret_cast<const float2*>(lnb + 128 + 2 * lane));
        float2 o;
        o.x = (ac.v[4] - mu1) * r1 * wv.x + bv.x;
        o.y = (ac.v[5] - mu1) * r1 * wv.y + bv.y;
        *reinterpret_cast<float2*>(row + 128 + 2 * lane) = o;
    }
    {   // field2: channels u = 4*lane + {0..3}
        const float4 wv = __ldg(reinterpret_cast<const float4*>(lnw + 192 + 4 * lane));
        const float sa = wv.x * r2, sb = wv.y * r2, sc = wv.z * r2, sd = wv.w * r2;
        float4 o1 = make_float4(ac.v[6]  * sa, ac.v[7]  * sa, ac.v[8]  * sa, ac.v[9]  * sb);
        float4 o2 = make_float4(ac.v[10] * sb, ac.v[11] * sb, ac.v[12] * sc, ac.v[13] * sc);
        float4 o3 = make_float4(ac.v[14] * sc, ac.v[15] * sd, ac.v[16] * sd, ac.v[17] * sd);
        *reinterpret_cast<float4*>(row + 192 + 12 * lane)     = o1;
        *reinterpret_cast<float4*>(row + 192 + 12 * lane + 4) = o2;
        *reinterpret_cast<float4*>(row + 192 + 12 * lane + 8) = o3;
    }
    {   // field3
        const float2 wv = __ldg(reinterpret_cast<const float2*>(lnw + 320 + 2 * lane));
        const float sa = wv.x * r3, sb = wv.y * r3;
        *reinterpret_cast<float2*>(row + 576 + 6 * lane)     = make_float2(ac.v[18] * sa, ac.v[19] * sa);
        *reinterpret_cast<float2*>(row + 576 + 6 * lane + 2) = make_float2(ac.v[20] * sa, ac.v[21] * sb);
        *reinterpret_cast<float2*>(row + 576 + 6 * lane + 4) = make_float2(ac.v[22] * sb, ac.v[23] * sb);
    }
    {   // field4
        const float2 wv = __ldg(reinterpret_cast<const float2*>(lnw + 384 + 2 * lane));
        const float sa = wv.x * r4, sb = wv.y * r4;
        *reinterpret_cast<float2*>(row + 768 + 6 * lane)     = make_float2(ac.v[24] * sa, ac.v[25] * sa);
        *reinterpret_cast<float2*>(row + 768 + 6 * lane + 2) = make_float2(ac.v[26] * sa, ac.v[27] * sb);
        *reinterpret_cast<float2*>(row + 768 + 6 * lane + 4) = make_float2(ac.v[28] * sb, ac.v[29] * sb);
    }
}

// ---------------------------------------------------------------------------
extern "C" void kernel_launch(void* const* d_in, const int* in_sizes, int n_in,
                              void* d_out, int out_size)
{
    const float* node_feat   = (const float*)d_in[0];
    const float* edge_sh     = (const float*)d_in[1];
    const float* edge_weight = (const float*)d_in[2];
    const float* tp_bias     = (const float*)d_in[3];
    const float* ln_weight   = (const float*)d_in[4];
    const float* ln_bias     = (const float*)d_in[5];
    const int*   edge_src    = (const int*)d_in[6];
    const int*   edge_dst    = (const int*)d_in[7];
    float* out = (float*)d_out;

    const int n_nodes = in_sizes[0] / 320;
    const int n_edges = in_sizes[7];

    {
        const int threads = (n_edges + 3) / 4;
        hist_count_kernel<<<(threads + 255) / 256, 256>>>(edge_dst, n_edges);
    }
    scan_kernel<<<1, 1024>>>(n_nodes);
    {
        const int threads = (n_edges + 3) / 4;
        scatter_kernel<<<(threads + 255) / 256, 256>>>(edge_dst, edge_src,
                                                       n_edges, n_nodes);
    }

    const int warps_per_block = 256 / 32;
    const int blocks = (n_nodes + warps_per_block - 1) / warps_per_block;
    fused_tp_ln_kernel<<<blocks, 256>>>(node_feat, edge_sh, edge_weight,
                                        tp_bias, ln_weight, ln_bias,
                                        out, n_nodes);
}

// round 8
// speedup vs baseline: 1.2043x; 1.0082x over previous
#include <cuda_runtime.h>
#include <cuda_bf16.h>
#include <cstdint>

#define INV_SQRT3 0.57735026918962576451f
#define INV_SQRT2 0.70710678118654752440f
#define LN_EPS 1e-5f

#define MAX_NODES 16384
#define MAX_EDGES 131072

// scratch (allocation-free rule: __device__ globals; statically zero-initialized)
__device__ int  g_hist[MAX_NODES];          // ALWAYS zero at kernel_launch entry
__device__ int  g_rank[MAX_EDGES];
__device__ int  g_start[MAX_NODES + 1];
__device__ int2 g_sorted2[MAX_EDGES];       // (edge_id, src_node)

__device__ __forceinline__ float warp_sum(float v) {
    v += __shfl_xor_sync(0xffffffffu, v, 16);
    v += __shfl_xor_sync(0xffffffffu, v, 8);
    v += __shfl_xor_sync(0xffffffffu, v, 4);
    v += __shfl_xor_sync(0xffffffffu, v, 2);
    v += __shfl_xor_sync(0xffffffffu, v, 1);
    return v;
}

// ---------------------------------------------------------------------------
// Sort pipeline: counting sort of edge ids by edge_dst (rank-based).
// ---------------------------------------------------------------------------
__global__ void hist_count_kernel(const int* __restrict__ edge_dst, int n_edges) {
    int i4 = (blockIdx.x * blockDim.x + threadIdx.x) * 4;
    if (i4 + 3 < n_edges) {
        const int4 d = *reinterpret_cast<const int4*>(edge_dst + i4);
        g_rank[i4 + 0] = atomicAdd(&g_hist[d.x], 1);
        g_rank[i4 + 1] = atomicAdd(&g_hist[d.y], 1);
        g_rank[i4 + 2] = atomicAdd(&g_hist[d.z], 1);
        g_rank[i4 + 3] = atomicAdd(&g_hist[d.w], 1);
    } else {
        for (int i = i4; i < n_edges; i++)
            g_rank[i] = atomicAdd(&g_hist[edge_dst[i]], 1);
    }
}

// single block, 1024 threads, 16 bins per thread (covers 16384 nodes)
__global__ void __launch_bounds__(1024) scan_kernel(int n_nodes) {
    __shared__ int ssum[1024];
    const int t = threadIdx.x;
    const int base = t * 16;

    int v[16];
    int s = 0;
#pragma unroll
    for (int i = 0; i < 16; i++) {
        int idx = base + i;
        v[i] = (idx < n_nodes) ? g_hist[idx] : 0;
        s += v[i];
    }
    ssum[t] = s;
    __syncthreads();

    for (int off = 1; off < 1024; off <<= 1) {
        int x = (t >= off) ? ssum[t - off] : 0;
        __syncthreads();
        ssum[t] += x;
        __syncthreads();
    }

    int run = (t == 0) ? 0 : ssum[t - 1];  // exclusive base
#pragma unroll
    for (int i = 0; i < 16; i++) {
        int idx = base + i;
        if (idx < n_nodes) g_start[idx] = run;
        run += v[i];
    }
    if (t == 1023) g_start[n_nodes] = run;
}

// atomic-free scatter using precomputed rank; stores (edge, src) pairs.
// Also restores g_hist to zero for the next kernel_launch call.
__global__ void scatter_kernel(const int* __restrict__ edge_dst,
                               const int* __restrict__ edge_src,
                               int n_edges, int n_nodes) {
    const int tid = blockIdx.x * blockDim.x + threadIdx.x;
    int i4 = tid * 4;
    if (i4 + 3 < n_edges) {
        const int4 d = *reinterpret_cast<const int4*>(edge_dst + i4);
        const int4 r = *reinterpret_cast<const int4*>(g_rank + i4);
        const int4 s = *reinterpret_cast<const int4*>(edge_src + i4);
        g_sorted2[__ldg(g_start + d.x) + r.x] = make_int2(i4 + 0, s.x);
        g_sorted2[__ldg(g_start + d.y) + r.y] = make_int2(i4 + 1, s.y);
        g_sorted2[__ldg(g_start + d.z) + r.z] = make_int2(i4 + 2, s.z);
        g_sorted2[__ldg(g_start + d.w) + r.w] = make_int2(i4 + 3, s.w);
    } else {
        for (int i = i4; i < n_edges; i++)
            g_sorted2[g_start[edge_dst[i]] + g_rank[i]] = make_int2(i, edge_src[i]);
    }
    // restore invariant: g_hist == 0 at next call's entry
    if (tid < n_nodes) g_hist[tid] = 0;
}

// ---------------------------------------------------------------------------
// Fused gather + depthwise TP + bias + equivariant LN.
// TWO warps per node, split by CHANNEL GROUP (fully independent — no smem,
// no cross-warp sync):
//   sub 0 (scalar path): loads xs,w0,w1  -> fields 0 (out0a) and 2 (out1a)
//   sub 1 (vector path): loads xv,w2..w4 -> fields 1 (out0b), 3 (out1b), 4 (out1c)
// Each warp walks the node's full edge list with a 2-edge unroll.
// ---------------------------------------------------------------------------
__global__ void __launch_bounds__(256, 3) fused_tp_ln_kernel(
    const float* __restrict__ node_feat,   // (N, 320)
    const float* __restrict__ edge_sh,     // (E, 4)
    const float* __restrict__ edge_weight, // (E, 448)
    const float* __restrict__ tp_bias,     // (192,)
    const float* __restrict__ lnw,         // (448,)
    const float* __restrict__ lnb,         // (192,)
    float*       __restrict__ out,         // (N, 960)
    int n_nodes)
{
    const int warpInBlock = threadIdx.x >> 5;   // 0..7
    const int lane = threadIdx.x & 31;
    const int node = blockIdx.x * 4 + (warpInBlock >> 1);
    const int sub  = warpInBlock & 1;
    if (node >= n_nodes) return;

    const int beg = g_start[node];
    const int end = g_start[node + 1];
    const int deg = end - beg;
    const float fdeg = (float)deg;

    float* row = out + (size_t)node * 960u;

    if (sub == 0) {
        // ================= scalar path: out0a (4) + out1a (12) ================
        float a0 = 0.f, a1 = 0.f, a2 = 0.f, a3 = 0.f;
        float A[12];
#pragma unroll
        for (int i = 0; i < 12; i++) A[i] = 0.f;

        int ei = beg;
        for (; ei + 1 < end; ei += 2) {
            const int2 es0 = __ldg(g_sorted2 + ei);
            const int2 es1 = __ldg(g_sorted2 + ei + 1);

            const float4 sh0 = __ldg(reinterpret_cast<const float4*>(edge_sh) + es0.x);
            const float4 sh1 = __ldg(reinterpret_cast<const float4*>(edge_sh) + es1.x);
            const float4 xs0 = __ldg(reinterpret_cast<const float4*>(node_feat + (size_t)es0.y * 320u) + lane);
            const float4 xs1 = __ldg(reinterpret_cast<const float4*>(node_feat + (size_t)es1.y * 320u) + lane);
            const float* wr0 = edge_weight + (size_t)es0.x * 448u;
            const float* wr1 = edge_weight + (size_t)es1.x * 448u;
            const float4 w00 = __ldg(reinterpret_cast<const float4*>(wr0) + lane);
            const float4 w01 = __ldg(reinterpret_cast<const float4*>(wr1) + lane);
            const float4 w10 = __ldg(reinterpret_cast<const float4*>(wr0 + 128) + lane);
            const float4 w11 = __ldg(reinterpret_cast<const float4*>(wr1 + 128) + lane);

            {
                const float ys = sh0.x;
                a0 += w00.x * xs0.x * ys; a1 += w00.y * xs0.y * ys;
                a2 += w00.z * xs0.z * ys; a3 += w00.w * xs0.w * ys;
                const float t0 = w10.x * xs0.x, t1 = w10.y * xs0.y;
                const float t2 = w10.z * xs0.z, t3 = w10.w * xs0.w;
                A[0] += t0 * sh0.y; A[1]  += t0 * sh0.z; A[2]  += t0 * sh0.w;
                A[3] += t1 * sh0.y; A[4]  += t1 * sh0.z; A[5]  += t1 * sh0.w;
                A[6] += t2 * sh0.y; A[7]  += t2 * sh0.z; A[8]  += t2 * sh0.w;
                A[9] += t3 * sh0.y; A[10] += t3 * sh0.z; A[11] += t3 * sh0.w;
            }
            {
                const float ys = sh1.x;
                a0 += w01.x * xs1.x * ys; a1 += w01.y * xs1.y * ys;
                a2 += w01.z * xs1.z * ys; a3 += w01.w * xs1.w * ys;
                const float t0 = w11.x * xs1.x, t1 = w11.y * xs1.y;
                const float t2 = w11.z * xs1.z, t3 = w11.w * xs1.w;
                A[0] += t0 * sh1.y; A[1]  += t0 * sh1.z; A[2]  += t0 * sh1.w;
                A[3] += t1 * sh1.y; A[4]  += t1 * sh1.z; A[5]  += t1 * sh1.w;
                A[6] += t2 * sh1.y; A[7]  += t2 * sh1.z; A[8]  += t2 * sh1.w;
                A[9] += t3 * sh1.y; A[10] += t3 * sh1.z; A[11] += t3 * sh1.w;
            }
        }
        if (ei < end) {
            const int2 es0 = __ldg(g_sorted2 + ei);
            const float4 sh0 = __ldg(reinterpret_cast<const float4*>(edge_sh) + es0.x);
            const float4 xs0 = __ldg(reinterpret_cast<const float4*>(node_feat + (size_t)es0.y * 320u) + lane);
            const float* wr0 = edge_weight + (size_t)es0.x * 448u;
            const float4 w00 = __ldg(reinterpret_cast<const float4*>(wr0) + lane);
            const float4 w10 = __ldg(reinterpret_cast<const float4*>(wr0 + 128) + lane);
            const float ys = sh0.x;
            a0 += w00.x * xs0.x * ys; a1 += w00.y * xs0.y * ys;
            a2 += w00.z * xs0.z * ys; a3 += w00.w * xs0.w * ys;
            const float t0 = w10.x * xs0.x, t1 = w10.y * xs0.y;
            const float t2 = w10.z * xs0.z, t3 = w10.w * xs0.w;
            A[0] += t0 * sh0.y; A[1]  += t0 * sh0.z; A[2]  += t0 * sh0.w;
            A[3] += t1 * sh0.y; A[4]  += t1 * sh0.z; A[5]  += t1 * sh0.w;
            A[6] += t2 * sh0.y; A[7]  += t2 * sh0.z; A[8]  += t2 * sh0.w;
            A[9] += t3 * sh0.y; A[10] += t3 * sh0.z; A[11] += t3 * sh0.w;
        }

        // bias (deg * per-edge bias)
        const float4 b0 = __ldg(reinterpret_cast<const float4*>(tp_bias) + lane);
        a0 += fdeg * b0.x; a1 += fdeg * b0.y; a2 += fdeg * b0.z; a3 += fdeg * b0.w;

        // LN stats for fields 0 and 2
        float s0 = a0 + a1 + a2 + a3;
        float q0 = a0 * a0 + a1 * a1 + a2 * a2 + a3 * a3;
        float q2 = 0.f;
#pragma unroll
        for (int i = 0; i < 12; i++) q2 += A[i] * A[i];
        s0 = warp_sum(s0); q0 = warp_sum(q0); q2 = warp_sum(q2);

        const float mu0 = s0 * (1.f / 128.f);
        const float r0  = rsqrtf(fmaxf(q0 * (1.f / 128.f) - mu0 * mu0, 0.f) + LN_EPS);
        const float r2  = rsqrtf(q2 * (1.f / 384.f) + LN_EPS);

        {   // field0
            const float4 wv = __ldg(reinterpret_cast<const float4*>(lnw) + lane);
            const float4 bv = __ldg(reinterpret_cast<const float4*>(lnb) + lane);
            float4 o;
            o.x = (a0 - mu0) * r0 * wv.x + bv.x;
            o.y = (a1 - mu0) * r0 * wv.y + bv.y;
            o.z = (a2 - mu0) * r0 * wv.z + bv.z;
            o.w = (a3 - mu0) * r0 * wv.w + bv.w;
            *reinterpret_cast<float4*>(row + 4 * lane) = o;
        }
        {   // field2: channels u = 4*lane + {0..3}
            const float4 wv = __ldg(reinterpret_cast<const float4*>(lnw + 192) + lane);
            const float sa = wv.x * r2, sb = wv.y * r2, sc = wv.z * r2, sd = wv.w * r2;
            *reinterpret_cast<float4*>(row + 192 + 12 * lane) =
                make_float4(A[0] * sa, A[1] * sa, A[2]  * sa, A[3]  * sb);
            *reinterpret_cast<float4*>(row + 192 + 12 * lane + 4) =
                make_float4(A[4] * sb, A[5] * sb, A[6]  * sc, A[7]  * sc);
            *reinterpret_cast<float4*>(row + 192 + 12 * lane + 8) =
                make_float4(A[8] * sc, A[9] * sd, A[10] * sd, A[11] * sd);
        }
    } else {
        // ============ vector path: out0b (2) + out1b (6) + out1c (6) ==========
        float ob0 = 0.f, ob1 = 0.f;
        float B[6], C[6];
#pragma unroll
        for (int i = 0; i < 6; i++) { B[i] = 0.f; C[i] = 0.f; }

        int ei = beg;
        for (; ei + 1 < end; ei += 2) {
            const int2 es0 = __ldg(g_sorted2 + ei);
            const int2 es1 = __ldg(g_sorted2 + ei + 1);

            const float4 sh0 = __ldg(reinterpret_cast<const float4*>(edge_sh) + es0.x);
            const float4 sh1 = __ldg(reinterpret_cast<const float4*>(edge_sh) + es1.x);
            const float* xr0 = node_feat + (size_t)es0.y * 320u + 128u;
            const float* xr1 = node_feat + (size_t)es1.y * 320u + 128u;
            const float* wr0 = edge_weight + (size_t)es0.x * 448u;
            const float* wr1 = edge_weight + (size_t)es1.x * 448u;

            const float2 w20 = __ldg(reinterpret_cast<const float2*>(wr0 + 256) + lane);
            const float2 w30 = __ldg(reinterpret_cast<const float2*>(wr0 + 320) + lane);
            const float2 w40 = __ldg(reinterpret_cast<const float2*>(wr0 + 384) + lane);
            const float2 p00 = __ldg(reinterpret_cast<const float2*>(xr0 + 6 * lane));
            const float2 p10 = __ldg(reinterpret_cast<const float2*>(xr0 + 6 * lane + 2));
            const float2 p20 = __ldg(reinterpret_cast<const float2*>(xr0 + 6 * lane + 4));

            const float2 w21 = __ldg(reinterpret_cast<const float2*>(wr1 + 256) + lane);
            const float2 w31 = __ldg(reinterpret_cast<const float2*>(wr1 + 320) + lane);
            const float2 w41 = __ldg(reinterpret_cast<const float2*>(wr1 + 384) + lane);
            const float2 p01 = __ldg(reinterpret_cast<const float2*>(xr1 + 6 * lane));
            const float2 p11 = __ldg(reinterpret_cast<const float2*>(xr1 + 6 * lane + 2));
            const float2 p21 = __ldg(reinterpret_cast<const float2*>(xr1 + 6 * lane + 4));

            {
                const float ys = sh0.x, yv0 = sh0.y, yv1 = sh0.z, yv2 = sh0.w;
                const float d0 = p00.x * yv0 + p00.y * yv1 + p10.x * yv2;
                const float d1 = p10.y * yv0 + p20.x * yv1 + p20.y * yv2;
                ob0 += w30.x * d0 * INV_SQRT3;
                ob1 += w30.y * d1 * INV_SQRT3;
                const float c0 = w20.x * ys, c1 = w20.y * ys;
                B[0] += c0 * p00.x; B[1] += c0 * p00.y; B[2] += c0 * p10.x;
                B[3] += c1 * p10.y; B[4] += c1 * p20.x; B[5] += c1 * p20.y;
                const float k0 = w40.x * INV_SQRT2, k1 = w40.y * INV_SQRT2;
                C[0] += k0 * (p00.y * yv2 - p10.x * yv1);
                C[1] += k0 * (p10.x * yv0 - p00.x * yv2);
                C[2] += k0 * (p00.x * yv1 - p00.y * yv0);
                C[3] += k1 * (p20.x * yv2 - p20.y * yv1);
                C[4] += k1 * (p20.y * yv0 - p10.y * yv2);
                C[5] += k1 * (p10.y * yv1 - p20.x * yv0);
            }
            {
                const float ys = sh1.x, yv0 = sh1.y, yv1 = sh1.z, yv2 = sh1.w;
                const float d0 = p01.x * yv0 + p01.y * yv1 + p11.x * yv2;
                const float d1 = p11.y * yv0 + p21.x * yv1 + p21.y * yv2;
                ob0 += w31.x * d0 * INV_SQRT3;
                ob1 += w31.y * d1 * INV_SQRT3;
                const float c0 = w21.x * ys, c1 = w21.y * ys;
                B[0] += c0 * p01.x; B[1] += c0 * p01.y; B[2] += c0 * p11.x;
                B[3] += c1 * p11.y; B[4] += c1 * p21.x; B[5] += c1 * p21.y;
                const float k0 = w41.x * INV_SQRT2, k1 = w41.y * INV_SQRT2;
                C[0] += k0 * (p01.y * yv2 - p11.x * yv1);
                C[1] += k0 * (p11.x * yv0 - p01.x * yv2);
                C[2] += k0 * (p01.x * yv1 - p01.y * yv0);
                C[3] += k1 * (p21.x * yv2 - p21.y * yv1);
                C[4] += k1 * (p21.y * yv0 - p11.y * yv2);
                C[5] += k1 * (p11.y * yv1 - p21.x * yv0);
            }
        }
        if (ei < end) {
            const int2 es0 = __ldg(g_sorted2 + ei);
            const float4 sh0 = __ldg(reinterpret_cast<const float4*>(edge_sh) + es0.x);
            const float* xr0 = node_feat + (size_t)es0.y * 320u + 128u;
            const float* wr0 = edge_weight + (size_t)es0.x * 448u;
            const float2 w20 = __ldg(reinterpret_cast<const float2*>(wr0 + 256) + lane);
            const float2 w30 = __ldg(reinterpret_cast<const float2*>(wr0 + 320) + lane);
            const float2 w40 = __ldg(reinterpret_cast<const float2*>(wr0 + 384) + lane);
            const float2 p00 = __ldg(reinterpret_cast<const float2*>(xr0 + 6 * lane));
            const float2 p10 = __ldg(reinterpret_cast<const float2*>(xr0 + 6 * lane + 2));
            const float2 p20 = __ldg(reinterpret_cast<const float2*>(xr0 + 6 * lane + 4));
            const float ys = sh0.x, yv0 = sh0.y, yv1 = sh0.z, yv2 = sh0.w;
            const float d0 = p00.x * yv0 + p00.y * yv1 + p10.x * yv2;
            const float d1 = p10.y * yv0 + p20.x * yv1 + p20.y * yv2;
            ob0 += w30.x * d0 * INV_SQRT3;
            ob1 += w30.y * d1 * INV_SQRT3;
            const float c0 = w20.x * ys, c1 = w20.y * ys;
            B[0] += c0 * p00.x; B[1] += c0 * p00.y; B[2] += c0 * p10.x;
            B[3] += c1 * p10.y; B[4] += c1 * p20.x; B[5] += c1 * p20.y;
            const float k0 = w40.x * INV_SQRT2, k1 = w40.y * INV_SQRT2;
            C[0] += k0 * (p00.y * yv2 - p10.x * yv1);
            C[1] += k0 * (p10.x * yv0 - p00.x * yv2);
            C[2] += k0 * (p00.x * yv1 - p00.y * yv0);
            C[3] += k1 * (p20.x * yv2 - p20.y * yv1);
            C[4] += k1 * (p20.y * yv0 - p10.y * yv2);
            C[5] += k1 * (p10.y * yv1 - p20.x * yv0);
        }

        // bias (deg * per-edge bias)
        const float2 bb = __ldg(reinterpret_cast<const float2*>(tp_bias + 128) + lane);
        ob0 += fdeg * bb.x; ob1 += fdeg * bb.y;

        // LN stats for fields 1, 3, 4
        float s1 = ob0 + ob1;
        float q1 = ob0 * ob0 + ob1 * ob1;
        float q3 = 0.f, q4 = 0.f;
#pragma unroll
        for (int i = 0; i < 6; i++) { q3 += B[i] * B[i]; q4 += C[i] * C[i]; }
        s1 = warp_sum(s1); q1 = warp_sum(q1);
        q3 = warp_sum(q3); q4 = warp_sum(q4);

        const float mu1 = s1 * (1.f / 64.f);
        const float r1  = rsqrtf(fmaxf(q1 * (1.f / 64.f) - mu1 * mu1, 0.f) + LN_EPS);
        const float r3  = rsqrtf(q3 * (1.f / 192.f) + LN_EPS);
        const float r4  = rsqrtf(q4 * (1.f / 192.f) + LN_EPS);

        {   // field1
            const float2 wv = __ldg(reinterpret_cast<const float2*>(lnw + 128) + lane);
            const float2 bv = __ldg(reinterpret_cast<const float2*>(lnb + 128) + lane);
            float2 o;
            o.x = (ob0 - mu1) * r1 * wv.x + bv.x;
            o.y = (ob1 - mu1) * r1 * wv.y + bv.y;
            *reinterpret_cast<float2*>(row + 128 + 2 * lane) = o;
        }
        {   // field3
            const float2 wv = __ldg(reinterpret_cast<const float2*>(lnw + 320) + lane);
            const float sa = wv.x * r3, sb = wv.y * r3;
            *reinterpret_cast<float2*>(row + 576 + 6 * lane)     = make_float2(B[0] * sa, B[1] * sa);
            *reinterpret_cast<float2*>(row + 576 + 6 * lane + 2) = make_float2(B[2] * sa, B[3] * sb);
            *reinterpret_cast<float2*>(row + 576 + 6 * lane + 4) = make_float2(B[4] * sb, B[5] * sb);
        }
        {   // field4
            const float2 wv = __ldg(reinterpret_cast<const float2*>(lnw + 384) + lane);
            const float sa = wv.x * r4, sb = wv.y * r4;
            *reinterpret_cast<float2*>(row + 768 + 6 * lane)     = make_float2(C[0] * sa, C[1] * sa);
            *reinterpret_cast<float2*>(row + 768 + 6 * lane + 2) = make_float2(C[2] * sa, C[3] * sb);
            *reinterpret_cast<float2*>(row + 768 + 6 * lane + 4) = make_float2(C[4] * sb, C[5] * sb);
        }
    }
}

// ---------------------------------------------------------------------------
extern "C" void kernel_launch(void* const* d_in, const int* in_sizes, int n_in,
                              void* d_out, int out_size)
{
    const float* node_feat   = (const float*)d_in[0];
    const float* edge_sh     = (const float*)d_in[1];
    const float* edge_weight = (const float*)d_in[2];
    const float* tp_bias     = (const float*)d_in[3];
    const float* ln_weight   = (const float*)d_in[4];
    const float* ln_bias     = (const float*)d_in[5];
    const int*   edge_src    = (const int*)d_in[6];
    const int*   edge_dst    = (const int*)d_in[7];
    float* out = (float*)d_out;

    const int n_nodes = in_sizes[0] / 320;
    const int n_edges = in_sizes[7];

    {
        const int threads = (n_edges + 3) / 4;
        hist_count_kernel<<<(threads + 255) / 256, 256>>>(edge_dst, n_edges);
    }
    scan_kernel<<<1, 1024>>>(n_nodes);
    {
        const int threads = (n_edges + 3) / 4;
        scatter_kernel<<<(threads + 255) / 256, 256>>>(edge_dst, edge_src,
                                                       n_edges, n_nodes);
    }

    // 2 warps per node (channel-split), 4 nodes per 256-thread block
    const int blocks = (n_nodes + 3) / 4;
    fused_tp_ln_kernel<<<blocks, 256>>>(node_feat, edge_sh, edge_weight,
                                        tp_bias, ln_weight, ln_bias,
                                        out, n_nodes);
}

// round 9
// speedup vs baseline: 1.3510x; 1.1218x over previous
#include <cuda_runtime.h>
#include <cuda_bf16.h>
#include <cstdint>

#define INV_SQRT3 0.57735026918962576451f
#define INV_SQRT2 0.70710678118654752440f
#define LN_EPS 1e-5f

#define MAX_NODES 16384
#define MAX_EDGES 131072

// scratch (allocation-free rule: __device__ globals; statically zero-initialized)
__device__ int  g_hist[MAX_NODES];          // ALWAYS zero at kernel_launch entry
__device__ int  g_rank[MAX_EDGES];
__device__ int  g_start[MAX_NODES + 1];
__device__ int2 g_sorted2[MAX_EDGES];       // (edge_id, src_node)

__device__ __forceinline__ float warp_sum(float v) {
    v += __shfl_xor_sync(0xffffffffu, v, 16);
    v += __shfl_xor_sync(0xffffffffu, v, 8);
    v += __shfl_xor_sync(0xffffffffu, v, 4);
    v += __shfl_xor_sync(0xffffffffu, v, 2);
    v += __shfl_xor_sync(0xffffffffu, v, 1);
    return v;
}

// ---------------------------------------------------------------------------
// Sort pipeline: counting sort of edge ids by edge_dst (rank-based).
// ---------------------------------------------------------------------------
// 2 edges per thread -> 256 blocks: maximize concurrent atomics across SMs
__global__ void hist_count_kernel(const int* __restrict__ edge_dst, int n_edges) {
    int i2 = (blockIdx.x * blockDim.x + threadIdx.x) * 2;
    if (i2 + 1 < n_edges) {
        const int2 d = *reinterpret_cast<const int2*>(edge_dst + i2);
        g_rank[i2 + 0] = atomicAdd(&g_hist[d.x], 1);
        g_rank[i2 + 1] = atomicAdd(&g_hist[d.y], 1);
    } else if (i2 < n_edges) {
        g_rank[i2] = atomicAdd(&g_hist[edge_dst[i2]], 1);
    }
}

// single block, 1024 threads, 16 bins per thread (covers 16384 nodes),
// int4-vectorized global loads/stores
__global__ void __launch_bounds__(1024) scan_kernel(int n_nodes) {
    __shared__ int ssum[1024];
    const int t = threadIdx.x;
    const int base = t * 16;

    int v[16];
    // vectorized read of 16 bins (n_nodes is a multiple of 4 in practice;
    // guard handles the generic case)
    if (base + 15 < n_nodes) {
#pragma unroll
        for (int c = 0; c < 4; c++) {
            const int4 h = *reinterpret_cast<const int4*>(g_hist + base + 4 * c);
            v[4 * c + 0] = h.x; v[4 * c + 1] = h.y;
            v[4 * c + 2] = h.z; v[4 * c + 3] = h.w;
        }
    } else {
#pragma unroll
        for (int i = 0; i < 16; i++) {
            int idx = base + i;
            v[i] = (idx < n_nodes) ? g_hist[idx] : 0;
        }
    }
    int s = 0;
#pragma unroll
    for (int i = 0; i < 16; i++) s += v[i];
    ssum[t] = s;
    __syncthreads();

    for (int off = 1; off < 1024; off <<= 1) {
        int x = (t >= off) ? ssum[t - off] : 0;
        __syncthreads();
        ssum[t] += x;
        __syncthreads();
    }

    int run = (t == 0) ? 0 : ssum[t - 1];  // exclusive base
    // turn v[] into exclusive prefix values in-place
    int pfx[16];
#pragma unroll
    for (int i = 0; i < 16; i++) { pfx[i] = run; run += v[i]; }

    if (base + 15 < n_nodes) {
#pragma unroll
        for (int c = 0; c < 4; c++) {
            *reinterpret_cast<int4*>(g_start + base + 4 * c) =
                make_int4(pfx[4 * c + 0], pfx[4 * c + 1], pfx[4 * c + 2], pfx[4 * c + 3]);
        }
    } else {
#pragma unroll
        for (int i = 0; i < 16; i++) {
            int idx = base + i;
            if (idx < n_nodes) g_start[idx] = pfx[i];
        }
    }
    if (t == 1023) g_start[n_nodes] = run;
}

// atomic-free scatter using precomputed rank; stores (edge, src) pairs.
// 2 edges per thread -> 256 blocks. Also re-zeros g_hist for the next call.
__global__ void scatter_kernel(const int* __restrict__ edge_dst,
                               const int* __restrict__ edge_src,
                               int n_edges, int n_nodes) {
    const int tid = blockIdx.x * blockDim.x + threadIdx.x;
    int i2 = tid * 2;
    if (i2 + 1 < n_edges) {
        const int2 d = *reinterpret_cast<const int2*>(edge_dst + i2);
        const int2 r = *reinterpret_cast<const int2*>(g_rank + i2);
        const int2 s = *reinterpret_cast<const int2*>(edge_src + i2);
        g_sorted2[__ldg(g_start + d.x) + r.x] = make_int2(i2 + 0, s.x);
        g_sorted2[__ldg(g_start + d.y) + r.y] = make_int2(i2 + 1, s.y);
    } else if (i2 < n_edges) {
        g_sorted2[g_start[edge_dst[i2]] + g_rank[i2]] = make_int2(i2, edge_src[i2]);
    }
    // restore invariant: g_hist == 0 at next call's entry
    if (tid < n_nodes) g_hist[tid] = 0;
}

// ---------------------------------------------------------------------------
// Fused gather + depthwise TP + bias + equivariant LN.
// TWO warps per node, split by CHANNEL GROUP (fully independent — no smem,
// no cross-warp sync):
//   sub 0 (scalar path): loads xs,w0,w1  -> fields 0 (out0a) and 2 (out1a)
//   sub 1 (vector path): loads xv,w2..w4 -> fields 1 (out0b), 3 (out1b), 4 (out1c)
// Each warp walks the node's full edge list with a 2-edge unroll.
// (At the pattern-limited DRAM roofline: 61% of 8 TB/s, traffic at floor.)
// ---------------------------------------------------------------------------
__global__ void __launch_bounds__(256, 3) fused_tp_ln_kernel(
    const float* __restrict__ node_feat,   // (N, 320)
    const float* __restrict__ edge_sh,     // (E, 4)
    const float* __restrict__ edge_weight, // (E, 448)
    const float* __restrict__ tp_bias,     // (192,)
    const float* __restrict__ lnw,         // (448,)
    const float* __restrict__ lnb,         // (192,)
    float*       __restrict__ out,         // (N, 960)
    int n_nodes)
{
    const int warpInBlock = threadIdx.x >> 5;   // 0..7
    const int lane = threadIdx.x & 31;
    const int node = blockIdx.x * 4 + (warpInBlock >> 1);
    const int sub  = warpInBlock & 1;
    if (node >= n_nodes) return;

    const int beg = g_start[node];
    const int end = g_start[node + 1];
    const int deg = end - beg;
    const float fdeg = (float)deg;

    float* row = out + (size_t)node * 960u;

    if (sub == 0) {
        // ================= scalar path: out0a (4) + out1a (12) ================
        float a0 = 0.f, a1 = 0.f, a2 = 0.f, a3 = 0.f;
        float A[12];
#pragma unroll
        for (int i = 0; i < 12; i++) A[i] = 0.f;

        int ei = beg;
        for (; ei + 1 < end; ei += 2) {
            const int2 es0 = __ldg(g_sorted2 + ei);
            const int2 es1 = __ldg(g_sorted2 + ei + 1);

            const float4 sh0 = __ldg(reinterpret_cast<const float4*>(edge_sh) + es0.x);
            const float4 sh1 = __ldg(reinterpret_cast<const float4*>(edge_sh) + es1.x);
            const float4 xs0 = __ldg(reinterpret_cast<const float4*>(node_feat + (size_t)es0.y * 320u) + lane);
            const float4 xs1 = __ldg(reinterpret_cast<const float4*>(node_feat + (size_t)es1.y * 320u) + lane);
            const float* wr0 = edge_weight + (size_t)es0.x * 448u;
            const float* wr1 = edge_weight + (size_t)es1.x * 448u;
            const float4 w00 = __ldg(reinterpret_cast<const float4*>(wr0) + lane);
            const float4 w01 = __ldg(reinterpret_cast<const float4*>(wr1) + lane);
            const float4 w10 = __ldg(reinterpret_cast<const float4*>(wr0 + 128) + lane);
            const float4 w11 = __ldg(reinterpret_cast<const float4*>(wr1 + 128) + lane);

            {
                const float ys = sh0.x;
                a0 += w00.x * xs0.x * ys; a1 += w00.y * xs0.y * ys;
                a2 += w00.z * xs0.z * ys; a3 += w00.w * xs0.w * ys;
                const float t0 = w10.x * xs0.x, t1 = w10.y * xs0.y;
                const float t2 = w10.z * xs0.z, t3 = w10.w * xs0.w;
                A[0] += t0 * sh0.y; A[1]  += t0 * sh0.z; A[2]  += t0 * sh0.w;
                A[3] += t1 * sh0.y; A[4]  += t1 * sh0.z; A[5]  += t1 * sh0.w;
                A[6] += t2 * sh0.y; A[7]  += t2 * sh0.z; A[8]  += t2 * sh0.w;
                A[9] += t3 * sh0.y; A[10] += t3 * sh0.z; A[11] += t3 * sh0.w;
            }
            {
                const float ys = sh1.x;
                a0 += w01.x * xs1.x * ys; a1 += w01.y * xs1.y * ys;
                a2 += w01.z * xs1.z * ys; a3 += w01.w * xs1.w * ys;
                const float t0 = w11.x * xs1.x, t1 = w11.y * xs1.y;
                const float t2 = w11.z * xs1.z, t3 = w11.w * xs1.w;
                A[0] += t0 * sh1.y; A[1]  += t0 * sh1.z; A[2]  += t0 * sh1.w;
                A[3] += t1 * sh1.y; A[4]  += t1 * sh1.z; A[5]  += t1 * sh1.w;
                A[6] += t2 * sh1.y; A[7]  += t2 * sh1.z; A[8]  += t2 * sh1.w;
                A[9] += t3 * sh1.y; A[10] += t3 * sh1.z; A[11] += t3 * sh1.w;
            }
        }
        if (ei < end) {
            const int2 es0 = __ldg(g_sorted2 + ei);
            const float4 sh0 = __ldg(reinterpret_cast<const float4*>(edge_sh) + es0.x);
            const float4 xs0 = __ldg(reinterpret_cast<const float4*>(node_feat + (size_t)es0.y * 320u) + lane);
            const float* wr0 = edge_weight + (size_t)es0.x * 448u;
            const float4 w00 = __ldg(reinterpret_cast<const float4*>(wr0) + lane);
            const float4 w10 = __ldg(reinterpret_cast<const float4*>(wr0 + 128) + lane);
            const float ys = sh0.x;
            a0 += w00.x * xs0.x * ys; a1 += w00.y * xs0.y * ys;
            a2 += w00.z * xs0.z * ys; a3 += w00.w * xs0.w * ys;
            const float t0 = w10.x * xs0.x, t1 = w10.y * xs0.y;
            const float t2 = w10.z * xs0.z, t3 = w10.w * xs0.w;
            A[0] += t0 * sh0.y; A[1]  += t0 * sh0.z; A[2]  += t0 * sh0.w;
            A[3] += t1 * sh0.y; A[4]  += t1 * sh0.z; A[5]  += t1 * sh0.w;
            A[6] += t2 * sh0.y; A[7]  += t2 * sh0.z; A[8]  += t2 * sh0.w;
            A[9] += t3 * sh0.y; A[10] += t3 * sh0.z; A[11] += t3 * sh0.w;
        }

        // bias (deg * per-edge bias)
        const float4 b0 = __ldg(reinterpret_cast<const float4*>(tp_bias) + lane);
        a0 += fdeg * b0.x; a1 += fdeg * b0.y; a2 += fdeg * b0.z; a3 += fdeg * b0.w;

        // LN stats for fields 0 and 2
        float s0 = a0 + a1 + a2 + a3;
        float q0 = a0 * a0 + a1 * a1 + a2 * a2 + a3 * a3;
        float q2 = 0.f;
#pragma unroll
        for (int i = 0; i < 12; i++) q2 += A[i] * A[i];
        s0 = warp_sum(s0); q0 = warp_sum(q0); q2 = warp_sum(q2);

        const float mu0 = s0 * (1.f / 128.f);
        const float r0  = rsqrtf(fmaxf(q0 * (1.f / 128.f) - mu0 * mu0, 0.f) + LN_EPS);
        const float r2  = rsqrtf(q2 * (1.f / 384.f) + LN_EPS);

        {   // field0
            const float4 wv = __ldg(reinterpret_cast<const float4*>(lnw) + lane);
            const float4 bv = __ldg(reinterpret_cast<const float4*>(lnb) + lane);
            float4 o;
            o.x = (a0 - mu0) * r0 * wv.x + bv.x;
            o.y = (a1 - mu0) * r0 * wv.y + bv.y;
            o.z = (a2 - mu0) * r0 * wv.z + bv.z;
            o.w = (a3 - mu0) * r0 * wv.w + bv.w;
            *reinterpret_cast<float4*>(row + 4 * lane) = o;
        }
        {   // field2: channels u = 4*lane + {0..3}
            const float4 wv = __ldg(reinterpret_cast<const float4*>(lnw + 192) + lane);
            const float sa = wv.x * r2, sb = wv.y * r2, sc = wv.z * r2, sd = wv.w * r2;
            *reinterpret_cast<float4*>(row + 192 + 12 * lane) =
                make_float4(A[0] * sa, A[1] * sa, A[2]  * sa, A[3]  * sb);
            *reinterpret_cast<float4*>(row + 192 + 12 * lane + 4) =
                make_float4(A[4] * sb, A[5] * sb, A[6]  * sc, A[7]  * sc);
            *reinterpret_cast<float4*>(row + 192 + 12 * lane + 8) =
                make_float4(A[8] * sc, A[9] * sd, A[10] * sd, A[11] * sd);
        }
    } else {
        // ============ vector path: out0b (2) + out1b (6) + out1c (6) ==========
        float ob0 = 0.f, ob1 = 0.f;
        float B[6], C[6];
#pragma unroll
        for (int i = 0; i < 6; i++) { B[i] = 0.f; C[i] = 0.f; }

        int ei = beg;
        for (; ei + 1 < end; ei += 2) {
            const int2 es0 = __ldg(g_sorted2 + ei);
            const int2 es1 = __ldg(g_sorted2 + ei + 1);

            const float4 sh0 = __ldg(reinterpret_cast<const float4*>(edge_sh) + es0.x);
            const float4 sh1 = __ldg(reinterpret_cast<const float4*>(edge_sh) + es1.x);
            const float* xr0 = node_feat + (size_t)es0.y * 320u + 128u;
            const float* xr1 = node_feat + (size_t)es1.y * 320u + 128u;
            const float* wr0 = edge_weight + (size_t)es0.x * 448u;
            const float* wr1 = edge_weight + (size_t)es1.x * 448u;

            const float2 w20 = __ldg(reinterpret_cast<const float2*>(wr0 + 256) + lane);
            const float2 w30 = __ldg(reinterpret_cast<const float2*>(wr0 + 320) + lane);
            const float2 w40 = __ldg(reinterpret_cast<const float2*>(wr0 + 384) + lane);
            const float2 p00 = __ldg(reinterpret_cast<const float2*>(xr0 + 6 * lane));
            const float2 p10 = __ldg(reinterpret_cast<const float2*>(xr0 + 6 * lane + 2));
            const float2 p20 = __ldg(reinterpret_cast<const float2*>(xr0 + 6 * lane + 4));

            const float2 w21 = __ldg(reinterpret_cast<const float2*>(wr1 + 256) + lane);
            const float2 w31 = __ldg(reinterpret_cast<const float2*>(wr1 + 320) + lane);
            const float2 w41 = __ldg(reinterpret_cast<const float2*>(wr1 + 384) + lane);
            const float2 p01 = __ldg(reinterpret_cast<const float2*>(xr1 + 6 * lane));
            const float2 p11 = __ldg(reinterpret_cast<const float2*>(xr1 + 6 * lane + 2));
            const float2 p21 = __ldg(reinterpret_cast<const float2*>(xr1 + 6 * lane + 4));

            {
                const float ys = sh0.x, yv0 = sh0.y, yv1 = sh0.z, yv2 = sh0.w;
                const float d0 = p00.x * yv0 + p00.y * yv1 + p10.x * yv2;
                const float d1 = p10.y * yv0 + p20.x * yv1 + p20.y * yv2;
                ob0 += w30.x * d0 * INV_SQRT3;
                ob1 += w30.y * d1 * INV_SQRT3;
                const float c0 = w20.x * ys, c1 = w20.y * ys;
                B[0] += c0 * p00.x; B[1] += c0 * p00.y; B[2] += c0 * p10.x;
                B[3] += c1 * p10.y; B[4] += c1 * p20.x; B[5] += c1 * p20.y;
                const float k0 = w40.x * INV_SQRT2, k1 = w40.y * INV_SQRT2;
                C[0] += k0 * (p00.y * yv2 - p10.x * yv1);
                C[1] += k0 * (p10.x * yv0 - p00.x * yv2);
                C[2] += k0 * (p00.x * yv1 - p00.y * yv0);
                C[3] += k1 * (p20.x * yv2 - p20.y * yv1);
                C[4] += k1 * (p20.y * yv0 - p10.y * yv2);
                C[5] += k1 * (p10.y * yv1 - p20.x * yv0);
            }
            {
                const float ys = sh1.x, yv0 = sh1.y, yv1 = sh1.z, yv2 = sh1.w;
                const float d0 = p01.x * yv0 + p01.y * yv1 + p11.x * yv2;
                const float d1 = p11.y * yv0 + p21.x * yv1 + p21.y * yv2;
                ob0 += w31.x * d0 * INV_SQRT3;
                ob1 += w31.y * d1 * INV_SQRT3;
                const float c0 = w21.x * ys, c1 = w21.y * ys;
                B[0] += c0 * p01.x; B[1] += c0 * p01.y; B[2] += c0 * p11.x;
                B[3] += c1 * p11.y; B[4] += c1 * p21.x; B[5] += c1 * p21.y;
                const float k0 = w41.x * INV_SQRT2, k1 = w41.y * INV_SQRT2;
                C[0] += k0 * (p01.y * yv2 - p11.x * yv1);
                C[1] += k0 * (p11.x * yv0 - p01.x * yv2);
                C[2] += k0 * (p01.x * yv1 - p01.y * yv0);
                C[3] += k1 * (p21.x * yv2 - p21.y * yv1);
                C[4] += k1 * (p21.y * yv0 - p11.y * yv2);
                C[5] += k1 * (p11.y * yv1 - p21.x * yv0);
            }
        }
        if (ei < end) {
            const int2 es0 = __ldg(g_sorted2 + ei);
            const float4 sh0 = __ldg(reinterpret_cast<const float4*>(edge_sh) + es0.x);
            const float* xr0 = node_feat + (size_t)es0.y * 320u + 128u;
            const float* wr0 = edge_weight + (size_t)es0.x * 448u;
            const float2 w20 = __ldg(reinterpret_cast<const float2*>(wr0 + 256) + lane);
            const float2 w30 = __ldg(reinterpret_cast<const float2*>(wr0 + 320) + lane);
            const float2 w40 = __ldg(reinterpret_cast<const float2*>(wr0 + 384) + lane);
            const float2 p00 = __ldg(reinterpret_cast<const float2*>(xr0 + 6 * lane));
            const float2 p10 = __ldg(reinterpret_cast<const float2*>(xr0 + 6 * lane + 2));
            const float2 p20 = __ldg(reinterpret_cast<const float2*>(xr0 + 6 * lane + 4));
            const float ys = sh0.x, yv0 = sh0.y, yv1 = sh0.z, yv2 = sh0.w;
            const float d0 = p00.x * yv0 + p00.y * yv1 + p10.x * yv2;
            const float d1 = p10.y * yv0 + p20.x * yv1 + p20.y * yv2;
            ob0 += w30.x * d0 * INV_SQRT3;
            ob1 += w30.y * d1 * INV_SQRT3;
            const float c0 = w20.x * ys, c1 = w20.y * ys;
            B[0] += c0 * p00.x; B[1] += c0 * p00.y; B[2] += c0 * p10.x;
            B[3] += c1 * p10.y; B[4] += c1 * p20.x; B[5] += c1 * p20.y;
            const float k0 = w40.x * INV_SQRT2, k1 = w40.y * INV_SQRT2;
            C[0] += k0 * (p00.y * yv2 - p10.x * yv1);
            C[1] += k0 * (p10.x * yv0 - p00.x * yv2);
            C[2] += k0 * (p00.x * yv1 - p00.y * yv0);
            C[3] += k1 * (p20.x * yv2 - p20.y * yv1);
            C[4] += k1 * (p20.y * yv0 - p10.y * yv2);
            C[5] += k1 * (p10.y * yv1 - p20.x * yv0);
        }

        // bias (deg * per-edge bias)
        const float2 bb = __ldg(reinterpret_cast<const float2*>(tp_bias + 128) + lane);
        ob0 += fdeg * bb.x; ob1 += fdeg * bb.y;

        // LN stats for fields 1, 3, 4
        float s1 = ob0 + ob1;
        float q1 = ob0 * ob0 + ob1 * ob1;
        float q3 = 0.f, q4 = 0.f;
#pragma unroll
        for (int i = 0; i < 6; i++) { q3 += B[i] * B[i]; q4 += C[i] * C[i]; }
        s1 = warp_sum(s1); q1 = warp_sum(q1);
        q3 = warp_sum(q3); q4 = warp_sum(q4);

        const float mu1 = s1 * (1.f / 64.f);
        const float r1  = rsqrtf(fmaxf(q1 * (1.f / 64.f) - mu1 * mu1, 0.f) + LN_EPS);
        const float r3  = rsqrtf(q3 * (1.f / 192.f) + LN_EPS);
        const float r4  = rsqrtf(q4 * (1.f / 192.f) + LN_EPS);

        {   // field1
            const float2 wv = __ldg(reinterpret_cast<const float2*>(lnw + 128) + lane);
            const float2 bv = __ldg(reinterpret_cast<const float2*>(lnb + 128) + lane);
            float2 o;
            o.x = (ob0 - mu1) * r1 * wv.x + bv.x;
            o.y = (ob1 - mu1) * r1 * wv.y + bv.y;
            *reinterpret_cast<float2*>(row + 128 + 2 * lane) = o;
        }
        {   // field3
            const float2 wv = __ldg(reinterpret_cast<const float2*>(lnw + 320) + lane);
            const float sa = wv.x * r3, sb = wv.y * r3;
            *reinterpret_cast<float2*>(row + 576 + 6 * lane)     = make_float2(B[0] * sa, B[1] * sa);
            *reinterpret_cast<float2*>(row + 576 + 6 * lane + 2) = make_float2(B[2] * sa, B[3] * sb);
            *reinterpret_cast<float2*>(row + 576 + 6 * lane + 4) = make_float2(B[4] * sb, B[5] * sb);
        }
        {   // field4
            const float2 wv = __ldg(reinterpret_cast<const float2*>(lnw + 384) + lane);
            const float sa = wv.x * r4, sb = wv.y * r4;
            *reinterpret_cast<float2*>(row + 768 + 6 * lane)     = make_float2(C[0] * sa, C[1] * sa);
            *reinterpret_cast<float2*>(row + 768 + 6 * lane + 2) = make_float2(C[2] * sa, C[3] * sb);
            *reinterpret_cast<float2*>(row + 768 + 6 * lane + 4) = make_float2(C[4] * sb, C[5] * sb);
        }
    }
}

// ---------------------------------------------------------------------------
extern "C" void kernel_launch(void* const* d_in, const int* in_sizes, int n_in,
                              void* d_out, int out_size)
{
    const float* node_feat   = (const float*)d_in[0];
    const float* edge_sh     = (const float*)d_in[1];
    const float* edge_weight = (const float*)d_in[2];
    const float* tp_bias     = (const float*)d_in[3];
    const float* ln_weight   = (const float*)d_in[4];
    const float* ln_bias     = (const float*)d_in[5];
    const int*   edge_src    = (const int*)d_in[6];
    const int*   edge_dst    = (const int*)d_in[7];
    float* out = (float*)d_out;

    const int n_nodes = in_sizes[0] / 320;
    const int n_edges = in_sizes[7];

    {
        const int threads = (n_edges + 1) / 2;
        hist_count_kernel<<<(threads + 255) / 256, 256>>>(edge_dst, n_edges);
    }
    scan_kernel<<<1, 1024>>>(n_nodes);
    {
        const int threads = (n_edges + 1) / 2;
        scatter_kernel<<<(threads + 255) / 256, 256>>>(edge_dst, edge_src,
                                                       n_edges, n_nodes);
    }

    // 2 warps per node (channel-split), 4 nodes per 256-thread block
    const int blocks = (n_nodes + 3) / 4;
    fused_tp_ln_kernel<<<blocks, 256>>>(node_feat, edge_sh, edge_weight,
                                        tp_bias, ln_weight, ln_bias,
                                        out, n_nodes);
}

// round 10
// speedup vs baseline: 1.5049x; 1.1139x over previous
#include <cuda_runtime.h>
#include <cuda_bf16.h>
#include <cstdint>

#define INV_SQRT3 0.57735026918962576451f
#define INV_SQRT2 0.70710678118654752440f
#define LN_EPS 1e-5f

#define MAX_NODES 16384
#define MAX_EDGES 131072

// scratch (allocation-free rule: __device__ globals; statically zero-initialized)
__device__ int  g_hist[MAX_NODES];          // ALWAYS zero at kernel_launch entry
__device__ int  g_rank[MAX_EDGES];
__device__ int  g_start[MAX_NODES + 1];
__device__ int2 g_sorted2[MAX_EDGES];       // (edge_id, src_node)

__device__ __forceinline__ float warp_sum(float v) {
    v += __shfl_xor_sync(0xffffffffu, v, 16);
    v += __shfl_xor_sync(0xffffffffu, v, 8);
    v += __shfl_xor_sync(0xffffffffu, v, 4);
    v += __shfl_xor_sync(0xffffffffu, v, 2);
    v += __shfl_xor_sync(0xffffffffu, v, 1);
    return v;
}

// ---------------------------------------------------------------------------
// Sort pipeline: counting sort of edge ids by edge_dst (rank-based).
// ---------------------------------------------------------------------------
__global__ void hist_count_kernel(const int* __restrict__ edge_dst, int n_edges) {
    int i2 = (blockIdx.x * blockDim.x + threadIdx.x) * 2;
    if (i2 + 1 < n_edges) {
        const int2 d = *reinterpret_cast<const int2*>(edge_dst + i2);
        g_rank[i2 + 0] = atomicAdd(&g_hist[d.x], 1);
        g_rank[i2 + 1] = atomicAdd(&g_hist[d.y], 1);
    } else if (i2 < n_edges) {
        g_rank[i2] = atomicAdd(&g_hist[edge_dst[i2]], 1);
    }
}

// single block, 1024 threads, 16 bins per thread; shuffle-based two-level
// scan (2 barriers instead of 20)
__global__ void __launch_bounds__(1024) scan_kernel(int n_nodes) {
    __shared__ int swarp[32];
    const int t = threadIdx.x;
    const int lane = t & 31;
    const int wid = t >> 5;
    const int base = t * 16;

    int v[16];
    if (base + 15 < n_nodes) {
#pragma unroll
        for (int c = 0; c < 4; c++) {
            const int4 h = *reinterpret_cast<const int4*>(g_hist + base + 4 * c);
            v[4 * c + 0] = h.x; v[4 * c + 1] = h.y;
            v[4 * c + 2] = h.z; v[4 * c + 3] = h.w;
        }
    } else {
#pragma unroll
        for (int i = 0; i < 16; i++) {
            int idx = base + i;
            v[i] = (idx < n_nodes) ? g_hist[idx] : 0;
        }
    }
    int s = 0;
#pragma unroll
    for (int i = 0; i < 16; i++) s += v[i];

    // inclusive scan of s within warp
    int inc = s;
#pragma unroll
    for (int off = 1; off < 32; off <<= 1) {
        int x = __shfl_up_sync(0xffffffffu, inc, off);
        if (lane >= off) inc += x;
    }
    if (lane == 31) swarp[wid] = inc;
    __syncthreads();

    // warp 0 scans the 32 warp totals
    if (wid == 0) {
        int w = swarp[lane];
        int winc = w;
#pragma unroll
        for (int off = 1; off < 32; off <<= 1) {
            int x = __shfl_up_sync(0xffffffffu, winc, off);
            if (lane >= off) winc += x;
        }
        swarp[lane] = winc - w;   // exclusive warp offset
    }
    __syncthreads();

    int run = swarp[wid] + (inc - s);  // exclusive prefix for this thread
    int pfx[16];
#pragma unroll
    for (int i = 0; i < 16; i++) { pfx[i] = run; run += v[i]; }

    if (base + 15 < n_nodes) {
#pragma unroll
        for (int c = 0; c < 4; c++) {
            *reinterpret_cast<int4*>(g_start + base + 4 * c) =
                make_int4(pfx[4 * c + 0], pfx[4 * c + 1], pfx[4 * c + 2], pfx[4 * c + 3]);
        }
    } else {
#pragma unroll
        for (int i = 0; i < 16; i++) {
            int idx = base + i;
            if (idx < n_nodes) g_start[idx] = pfx[i];
        }
    }
    if (t == 1023) g_start[n_nodes] = run;
}

// atomic-free scatter using precomputed rank; stores (edge, src) pairs.
// Also restores g_hist to zero for the next call.
__global__ void scatter_kernel(const int* __restrict__ edge_dst,
                               const int* __restrict__ edge_src,
                               int n_edges, int n_nodes) {
    const int tid = blockIdx.x * blockDim.x + threadIdx.x;
    int i2 = tid * 2;
    if (i2 + 1 < n_edges) {
        const int2 d = *reinterpret_cast<const int2*>(edge_dst + i2);
        const int2 r = *reinterpret_cast<const int2*>(g_rank + i2);
        const int2 s = *reinterpret_cast<const int2*>(edge_src + i2);
        g_sorted2[__ldg(g_start + d.x) + r.x] = make_int2(i2 + 0, s.x);
        g_sorted2[__ldg(g_start + d.y) + r.y] = make_int2(i2 + 1, s.y);
    } else if (i2 < n_edges) {
        g_sorted2[g_start[edge_dst[i2]] + g_rank[i2]] = make_int2(i2, edge_src[i2]);
    }
    if (tid < n_nodes) g_hist[tid] = 0;
}

// ---------------------------------------------------------------------------
// Fused gather + depthwise TP + bias + equivariant LN.
// TWO warps per node, split by CHANNEL GROUP (fully independent):
//   sub 0 (scalar path): loads xs,w0,w1  -> fields 0 (out0a) and 2 (out1a)
//   sub 1 (vector path): loads xv,w2..w4 -> fields 1 (out0b), 3 (out1b), 4 (out1c)
// edge_weight is read-once -> __ldcs (evict-first); outputs -> __stcs.
// ---------------------------------------------------------------------------
__global__ void __launch_bounds__(256, 3) fused_tp_ln_kernel(
    const float* __restrict__ node_feat,   // (N, 320)
    const float* __restrict__ edge_sh,     // (E, 4)
    const float* __restrict__ edge_weight, // (E, 448)
    const float* __restrict__ tp_bias,     // (192,)
    const float* __restrict__ lnw,         // (448,)
    const float* __restrict__ lnb,         // (192,)
    float*       __restrict__ out,         // (N, 960)
    int n_nodes)
{
    const int warpInBlock = threadIdx.x >> 5;   // 0..7
    const int lane = threadIdx.x & 31;
    const int node = blockIdx.x * 4 + (warpInBlock >> 1);
    const int sub  = warpInBlock & 1;
    if (node >= n_nodes) return;

    const int beg = g_start[node];
    const int end = g_start[node + 1];
    const int deg = end - beg;
    const float fdeg = (float)deg;

    float* row = out + (size_t)node * 960u;

    if (sub == 0) {
        // ================= scalar path: out0a (4) + out1a (12) ================
        float a0 = 0.f, a1 = 0.f, a2 = 0.f, a3 = 0.f;
        float A[12];
#pragma unroll
        for (int i = 0; i < 12; i++) A[i] = 0.f;

        int ei = beg;
        for (; ei + 1 < end; ei += 2) {
            const int2 es0 = __ldg(g_sorted2 + ei);
            const int2 es1 = __ldg(g_sorted2 + ei + 1);

            const float4 sh0 = __ldg(reinterpret_cast<const float4*>(edge_sh) + es0.x);
            const float4 sh1 = __ldg(reinterpret_cast<const float4*>(edge_sh) + es1.x);
            const float4 xs0 = __ldg(reinterpret_cast<const float4*>(node_feat + (size_t)es0.y * 320u) + lane);
            const float4 xs1 = __ldg(reinterpret_cast<const float4*>(node_feat + (size_t)es1.y * 320u) + lane);
            const float* wr0 = edge_weight + (size_t)es0.x * 448u;
            const float* wr1 = edge_weight + (size_t)es1.x * 448u;
            const float4 w00 = __ldcs(reinterpret_cast<const float4*>(wr0) + lane);
            const float4 w01 = __ldcs(reinterpret_cast<const float4*>(wr1) + lane);
            const float4 w10 = __ldcs(reinterpret_cast<const float4*>(wr0 + 128) + lane);
            const float4 w11 = __ldcs(reinterpret_cast<const float4*>(wr1 + 128) + lane);

            {
                const float ys = sh0.x;
                a0 += w00.x * xs0.x * ys; a1 += w00.y * xs0.y * ys;
                a2 += w00.z * xs0.z * ys; a3 += w00.w * xs0.w * ys;
                const float t0 = w10.x * xs0.x, t1 = w10.y * xs0.y;
                const float t2 = w10.z * xs0.z, t3 = w10.w * xs0.w;
                A[0] += t0 * sh0.y; A[1]  += t0 * sh0.z; A[2]  += t0 * sh0.w;
                A[3] += t1 * sh0.y; A[4]  += t1 * sh0.z; A[5]  += t1 * sh0.w;
                A[6] += t2 * sh0.y; A[7]  += t2 * sh0.z; A[8]  += t2 * sh0.w;
                A[9] += t3 * sh0.y; A[10] += t3 * sh0.z; A[11] += t3 * sh0.w;
            }
            {
                const float ys = sh1.x;
                a0 += w01.x * xs1.x * ys; a1 += w01.y * xs1.y * ys;
                a2 += w01.z * xs1.z * ys; a3 += w01.w * xs1.w * ys;
                const float t0 = w11.x * xs1.x, t1 = w11.y * xs1.y;
                const float t2 = w11.z * xs1.z, t3 = w11.w * xs1.w;
                A[0] += t0 * sh1.y; A[1]  += t0 * sh1.z; A[2]  += t0 * sh1.w;
                A[3] += t1 * sh1.y; A[4]  += t1 * sh1.z; A[5]  += t1 * sh1.w;
                A[6] += t2 * sh1.y; A[7]  += t2 * sh1.z; A[8]  += t2 * sh1.w;
                A[9] += t3 * sh1.y; A[10] += t3 * sh1.z; A[11] += t3 * sh1.w;
            }
        }
        if (ei < end) {
            const int2 es0 = __ldg(g_sorted2 + ei);
            const float4 sh0 = __ldg(reinterpret_cast<const float4*>(edge_sh) + es0.x);
            const float4 xs0 = __ldg(reinterpret_cast<const float4*>(node_feat + (size_t)es0.y * 320u) + lane);
            const float* wr0 = edge_weight + (size_t)es0.x * 448u;
            const float4 w00 = __ldcs(reinterpret_cast<const float4*>(wr0) + lane);
            const float4 w10 = __ldcs(reinterpret_cast<const float4*>(wr0 + 128) + lane);
            const float ys = sh0.x;
            a0 += w00.x * xs0.x * ys; a1 += w00.y * xs0.y * ys;
            a2 += w00.z * xs0.z * ys; a3 += w00.w * xs0.w * ys;
            const float t0 = w10.x * xs0.x, t1 = w10.y * xs0.y;
            const float t2 = w10.z * xs0.z, t3 = w10.w * xs0.w;
            A[0] += t0 * sh0.y; A[1]  += t0 * sh0.z; A[2]  += t0 * sh0.w;
            A[3] += t1 * sh0.y; A[4]  += t1 * sh0.z; A[5]  += t1 * sh0.w;
            A[6] += t2 * sh0.y; A[7]  += t2 * sh0.z; A[8]  += t2 * sh0.w;
            A[9] += t3 * sh0.y; A[10] += t3 * sh0.z; A[11] += t3 * sh0.w;
        }

        const float4 b0 = __ldg(reinterpret_cast<const float4*>(tp_bias) + lane);
        a0 += fdeg * b0.x; a1 += fdeg * b0.y; a2 += fdeg * b0.z; a3 += fdeg * b0.w;

        float s0 = a0 + a1 + a2 + a3;
        float q0 = a0 * a0 + a1 * a1 + a2 * a2 + a3 * a3;
        float q2 = 0.f;
#pragma unroll
        for (int i = 0; i < 12; i++) q2 += A[i] * A[i];
        s0 = warp_sum(s0); q0 = warp_sum(q0); q2 = warp_sum(q2);

        const float mu0 = s0 * (1.f / 128.f);
        const float r0  = rsqrtf(fmaxf(q0 * (1.f / 128.f) - mu0 * mu0, 0.f) + LN_EPS);
        const float r2  = rsqrtf(q2 * (1.f / 384.f) + LN_EPS);

        {   // field0
            const float4 wv = __ldg(reinterpret_cast<const float4*>(lnw) + lane);
            const float4 bv = __ldg(reinterpret_cast<const float4*>(lnb) + lane);
            float4 o;
            o.x = (a0 - mu0) * r0 * wv.x + bv.x;
            o.y = (a1 - mu0) * r0 * wv.y + bv.y;
            o.z = (a2 - mu0) * r0 * wv.z + bv.z;
            o.w = (a3 - mu0) * r0 * wv.w + bv.w;
            __stcs(reinterpret_cast<float4*>(row + 4 * lane), o);
        }
        {   // field2: channels u = 4*lane + {0..3}
            const float4 wv = __ldg(reinterpret_cast<const float4*>(lnw + 192) + lane);
            const float sa = wv.x * r2, sb = wv.y * r2, sc = wv.z * r2, sd = wv.w * r2;
            __stcs(reinterpret_cast<float4*>(row + 192 + 12 * lane),
                   make_float4(A[0] * sa, A[1] * sa, A[2]  * sa, A[3]  * sb));
            __stcs(reinterpret_cast<float4*>(row + 192 + 12 * lane + 4),
                   make_float4(A[4] * sb, A[5] * sb, A[6]  * sc, A[7]  * sc));
            __stcs(reinterpret_cast<float4*>(row + 192 + 12 * lane + 8),
                   make_float4(A[8] * sc, A[9] * sd, A[10] * sd, A[11] * sd));
        }
    } else {
        // ============ vector path: out0b (2) + out1b (6) + out1c (6) ==========
        float ob0 = 0.f, ob1 = 0.f;
        float B[6], C[6];
#pragma unroll
        for (int i = 0; i < 6; i++) { B[i] = 0.f; C[i] = 0.f; }

        int ei = beg;
        for (; ei + 1 < end; ei += 2) {
            const int2 es0 = __ldg(g_sorted2 + ei);
            const int2 es1 = __ldg(g_sorted2 + ei + 1);

            const float4 sh0 = __ldg(reinterpret_cast<const float4*>(edge_sh) + es0.x);
            const float4 sh1 = __ldg(reinterpret_cast<const float4*>(edge_sh) + es1.x);
            const float* xr0 = node_feat + (size_t)es0.y * 320u + 128u;
            const float* xr1 = node_feat + (size_t)es1.y * 320u + 128u;
            const float* wr0 = edge_weight + (size_t)es0.x * 448u;
            const float* wr1 = edge_weight + (size_t)es1.x * 448u;

            const float2 w20 = __ldcs(reinterpret_cast<const float2*>(wr0 + 256) + lane);
            const float2 w30 = __ldcs(reinterpret_cast<const float2*>(wr0 + 320) + lane);
            const float2 w40 = __ldcs(reinterpret_cast<const float2*>(wr0 + 384) + lane);
            const float2 p00 = __ldg(reinterpret_cast<const float2*>(xr0 + 6 * lane));
            const float2 p10 = __ldg(reinterpret_cast<const float2*>(xr0 + 6 * lane + 2));
            const float2 p20 = __ldg(reinterpret_cast<const float2*>(xr0 + 6 * lane + 4));

            const float2 w21 = __ldcs(reinterpret_cast<const float2*>(wr1 + 256) + lane);
            const float2 w31 = __ldcs(reinterpret_cast<const float2*>(wr1 + 320) + lane);
            const float2 w41 = __ldcs(reinterpret_cast<const float2*>(wr1 + 384) + lane);
            const float2 p01 = __ldg(reinterpret_cast<const float2*>(xr1 + 6 * lane));
            const float2 p11 = __ldg(reinterpret_cast<const float2*>(xr1 + 6 * lane + 2));
            const float2 p21 = __ldg(reinterpret_cast<const float2*>(xr1 + 6 * lane + 4));

            {
                const float ys = sh0.x, yv0 = sh0.y, yv1 = sh0.z, yv2 = sh0.w;
                const float d0 = p00.x * yv0 + p00.y * yv1 + p10.x * yv2;
                const float d1 = p10.y * yv0 + p20.x * yv1 + p20.y * yv2;
                ob0 += w30.x * d0 * INV_SQRT3;
                ob1 += w30.y * d1 * INV_SQRT3;
                const float c0 = w20.x * ys, c1 = w20.y * ys;
                B[0] += c0 * p00.x; B[1] += c0 * p00.y; B[2] += c0 * p10.x;
                B[3] += c1 * p10.y; B[4] += c1 * p20.x; B[5] += c1 * p20.y;
                const float k0 = w40.x * INV_SQRT2, k1 = w40.y * INV_SQRT2;
                C[0] += k0 * (p00.y * yv2 - p10.x * yv1);
                C[1] += k0 * (p10.x * yv0 - p00.x * yv2);
                C[2] += k0 * (p00.x * yv1 - p00.y * yv0);
                C[3] += k1 * (p20.x * yv2 - p20.y * yv1);
                C[4] += k1 * (p20.y * yv0 - p10.y * yv2);
                C[5] += k1 * (p10.y * yv1 - p20.x * yv0);
            }
            {
                const float ys = sh1.x, yv0 = sh1.y, yv1 = sh1.z, yv2 = sh1.w;
                const float d0 = p01.x * yv0 + p01.y * yv1 + p11.x * yv2;
                const float d1 = p11.y * yv0 + p21.x * yv1 + p21.y * yv2;
                ob0 += w31.x * d0 * INV_SQRT3;
                ob1 += w31.y * d1 * INV_SQRT3;
                const float c0 = w21.x * ys, c1 = w21.y * ys;
                B[0] += c0 * p01.x; B[1] += c0 * p01.y; B[2] += c0 * p11.x;
                B[3] += c1 * p11.y; B[4] += c1 * p21.x; B[5] += c1 * p21.y;
                const float k0 = w41.x * INV_SQRT2, k1 = w41.y * INV_SQRT2;
                C[0] += k0 * (p01.y * yv2 - p11.x * yv1);
                C[1] += k0 * (p11.x * yv0 - p01.x * yv2);
                C[2] += k0 * (p01.x * yv1 - p01.y * yv0);
                C[3] += k1 * (p21.x * yv2 - p21.y * yv1);
                C[4] += k1 * (p21.y * yv0 - p11.y * yv2);
                C[5] += k1 * (p11.y * yv1 - p21.x * yv0);
            }
        }
        if (ei < end) {
            const int2 es0 = __ldg(g_sorted2 + ei);
            const float4 sh0 = __ldg(reinterpret_cast<const float4*>(edge_sh) + es0.x);
            const float* xr0 = node_feat + (size_t)es0.y * 320u + 128u;
            const float* wr0 = edge_weight + (size_t)es0.x * 448u;
            const float2 w20 = __ldcs(reinterpret_cast<const float2*>(wr0 + 256) + lane);
            const float2 w30 = __ldcs(reinterpret_cast<const float2*>(wr0 + 320) + lane);
            const float2 w40 = __ldcs(reinterpret_cast<const float2*>(wr0 + 384) + lane);
            const float2 p00 = __ldg(reinterpret_cast<const float2*>(xr0 + 6 * lane));
            const float2 p10 = __ldg(reinterpret_cast<const float2*>(xr0 + 6 * lane + 2));
            const float2 p20 = __ldg(reinterpret_cast<const float2*>(xr0 + 6 * lane + 4));
            const float ys = sh0.x, yv0 = sh0.y, yv1 = sh0.z, yv2 = sh0.w;
            const float d0 = p00.x * yv0 + p00.y * yv1 + p10.x * yv2;
            const float d1 = p10.y * yv0 + p20.x * yv1 + p20.y * yv2;
            ob0 += w30.x * d0 * INV_SQRT3;
            ob1 += w30.y * d1 * INV_SQRT3;
            const float c0 = w20.x * ys, c1 = w20.y * ys;
            B[0] += c0 * p00.x; B[1] += c0 * p00.y; B[2] += c0 * p10.x;
            B[3] += c1 * p10.y; B[4] += c1 * p20.x; B[5] += c1 * p20.y;
            const float k0 = w40.x * INV_SQRT2, k1 = w40.y * INV_SQRT2;
            C[0] += k0 * (p00.y * yv2 - p10.x * yv1);
            C[1] += k0 * (p10.x * yv0 - p00.x * yv2);
            C[2] += k0 * (p00.x * yv1 - p00.y * yv0);
            C[3] += k1 * (p20.x * yv2 - p20.y * yv1);
            C[4] += k1 * (p20.y * yv0 - p10.y * yv2);
            C[5] += k1 * (p10.y * yv1 - p20.x * yv0);
        }

        const float2 bb = __ldg(reinterpret_cast<const float2*>(tp_bias + 128) + lane);
        ob0 += fdeg * bb.x; ob1 += fdeg * bb.y;

        float s1 = ob0 + ob1;
        float q1 = ob0 * ob0 + ob1 * ob1;
        float q3 = 0.f, q4 = 0.f;
#pragma unroll
        for (int i = 0; i < 6; i++) { q3 += B[i] * B[i]; q4 += C[i] * C[i]; }
        s1 = warp_sum(s1); q1 = warp_sum(q1);
        q3 = warp_sum(q3); q4 = warp_sum(q4);

        const float mu1 = s1 * (1.f / 64.f);
        const float r1  = rsqrtf(fmaxf(q1 * (1.f / 64.f) - mu1 * mu1, 0.f) + LN_EPS);
        const float r3  = rsqrtf(q3 * (1.f / 192.f) + LN_EPS);
        const float r4  = rsqrtf(q4 * (1.f / 192.f) + LN_EPS);

        {   // field1
            const float2 wv = __ldg(reinterpret_cast<const float2*>(lnw + 128) + lane);
            const float2 bv = __ldg(reinterpret_cast<const float2*>(lnb + 128) + lane);
            float2 o;
            o.x = (ob0 - mu1) * r1 * wv.x + bv.x;
            o.y = (ob1 - mu1) * r1 * wv.y + bv.y;
            __stcs(reinterpret_cast<float2*>(row + 128 + 2 * lane), o);
        }
        {   // field3
            const float2 wv = __ldg(reinterpret_cast<const float2*>(lnw + 320) + lane);
            const float sa = wv.x * r3, sb = wv.y * r3;
            __stcs(reinterpret_cast<float2*>(row + 576 + 6 * lane),     make_float2(B[0] * sa, B[1] * sa));
            __stcs(reinterpret_cast<float2*>(row + 576 + 6 * lane + 2), make_float2(B[2] * sa, B[3] * sb));
            __stcs(reinterpret_cast<float2*>(row + 576 + 6 * lane + 4), make_float2(B[4] * sb, B[5] * sb));
        }
        {   // field4
            const float2 wv = __ldg(reinterpret_cast<const float2*>(lnw + 384) + lane);
            const float sa = wv.x * r4, sb = wv.y * r4;
            __stcs(reinterpret_cast<float2*>(row + 768 + 6 * lane),     make_float2(C[0] * sa, C[1] * sa));
            __stcs(reinterpret_cast<float2*>(row + 768 + 6 * lane + 2), make_float2(C[2] * sa, C[3] * sb));
            __stcs(reinterpret_cast<float2*>(row + 768 + 6 * lane + 4), make_float2(C[4] * sb, C[5] * sb));
        }
    }
}

// ---------------------------------------------------------------------------
extern "C" void kernel_launch(void* const* d_in, const int* in_sizes, int n_in,
                              void* d_out, int out_size)
{
    const float* node_feat   = (const float*)d_in[0];
    const float* edge_sh     = (const float*)d_in[1];
    const float* edge_weight = (const float*)d_in[2];
    const float* tp_bias     = (const float*)d_in[3];
    const float* ln_weight   = (const float*)d_in[4];
    const float* ln_bias     = (const float*)d_in[5];
    const int*   edge_src    = (const int*)d_in[6];
    const int*   edge_dst    = (const int*)d_in[7];
    float* out = (float*)d_out;

    const int n_nodes = in_sizes[0] / 320;
    const int n_edges = in_sizes[7];

    {
        const int threads = (n_edges + 1) / 2;
        hist_count_kernel<<<(threads + 255) / 256, 256>>>(edge_dst, n_edges);
    }
    scan_kernel<<<1, 1024>>>(n_nodes);
    {
        const int threads = (n_edges + 1) / 2;
        scatter_kernel<<<(threads + 255) / 256, 256>>>(edge_dst, edge_src,
                                                       n_edges, n_nodes);
    }

    // 2 warps per node (channel-split), 4 nodes per 256-thread block
    const int blocks = (n_nodes + 3) / 4;
    fused_tp_ln_kernel<<<blocks, 256>>>(node_feat, edge_sh, edge_weight,
                                        tp_bias, ln_weight, ln_bias,
                                        out, n_nodes);
}

// round 11
// speedup vs baseline: 1.5432x; 1.0255x over previous
#include <cuda_runtime.h>
#include <cuda_bf16.h>
#include <cstdint>

#define INV_SQRT3 0.57735026918962576451f
#define INV_SQRT2 0.70710678118654752440f
#define LN_EPS 1e-5f

#define MAX_NODES 16384
#define MAX_EDGES 131072

// scratch (allocation-free rule: __device__ globals; statically zero-initialized)
__device__ int  g_hist[MAX_NODES];          // ALWAYS zero at kernel_launch entry
__device__ int  g_rank[MAX_EDGES];
__device__ int  g_start[MAX_NODES + 1];
__device__ int2 g_sorted2[MAX_EDGES];       // (edge_id, src_node)

__device__ __forceinline__ float warp_sum(float v) {
    v += __shfl_xor_sync(0xffffffffu, v, 16);
    v += __shfl_xor_sync(0xffffffffu, v, 8);
    v += __shfl_xor_sync(0xffffffffu, v, 4);
    v += __shfl_xor_sync(0xffffffffu, v, 2);
    v += __shfl_xor_sync(0xffffffffu, v, 1);
    return v;
}

// ---------------------------------------------------------------------------
// Sort pipeline: counting sort of edge ids by edge_dst (rank-based).
// ---------------------------------------------------------------------------
__global__ void hist_count_kernel(const int* __restrict__ edge_dst, int n_edges) {
    int i2 = (blockIdx.x * blockDim.x + threadIdx.x) * 2;
    if (i2 + 1 < n_edges) {
        const int2 d = *reinterpret_cast<const int2*>(edge_dst + i2);
        g_rank[i2 + 0] = atomicAdd(&g_hist[d.x], 1);
        g_rank[i2 + 1] = atomicAdd(&g_hist[d.y], 1);
    } else if (i2 < n_edges) {
        g_rank[i2] = atomicAdd(&g_hist[edge_dst[i2]], 1);
    }
}

// single block, 1024 threads, 16 bins per thread; shuffle-based two-level scan
__global__ void __launch_bounds__(1024) scan_kernel(int n_nodes) {
    __shared__ int swarp[32];
    const int t = threadIdx.x;
    const int lane = t & 31;
    const int wid = t >> 5;
    const int base = t * 16;

    int v[16];
    if (base + 15 < n_nodes) {
#pragma unroll
        for (int c = 0; c < 4; c++) {
            const int4 h = *reinterpret_cast<const int4*>(g_hist + base + 4 * c);
            v[4 * c + 0] = h.x; v[4 * c + 1] = h.y;
            v[4 * c + 2] = h.z; v[4 * c + 3] = h.w;
        }
    } else {
#pragma unroll
        for (int i = 0; i < 16; i++) {
            int idx = base + i;
            v[i] = (idx < n_nodes) ? g_hist[idx] : 0;
        }
    }
    int s = 0;
#pragma unroll
    for (int i = 0; i < 16; i++) s += v[i];

    int inc = s;
#pragma unroll
    for (int off = 1; off < 32; off <<= 1) {
        int x = __shfl_up_sync(0xffffffffu, inc, off);
        if (lane >= off) inc += x;
    }
    if (lane == 31) swarp[wid] = inc;
    __syncthreads();

    if (wid == 0) {
        int w = swarp[lane];
        int winc = w;
#pragma unroll
        for (int off = 1; off < 32; off <<= 1) {
            int x = __shfl_up_sync(0xffffffffu, winc, off);
            if (lane >= off) winc += x;
        }
        swarp[lane] = winc - w;
    }
    __syncthreads();

    int run = swarp[wid] + (inc - s);
    int pfx[16];
#pragma unroll
    for (int i = 0; i < 16; i++) { pfx[i] = run; run += v[i]; }

    if (base + 15 < n_nodes) {
#pragma unroll
        for (int c = 0; c < 4; c++) {
            *reinterpret_cast<int4*>(g_start + base + 4 * c) =
                make_int4(pfx[4 * c + 0], pfx[4 * c + 1], pfx[4 * c + 2], pfx[4 * c + 3]);
        }
    } else {
#pragma unroll
        for (int i = 0; i < 16; i++) {
            int idx = base + i;
            if (idx < n_nodes) g_start[idx] = pfx[i];
        }
    }
    if (t == 1023) g_start[n_nodes] = run;
}

__global__ void scatter_kernel(const int* __restrict__ edge_dst,
                               const int* __restrict__ edge_src,
                               int n_edges, int n_nodes) {
    const int tid = blockIdx.x * blockDim.x + threadIdx.x;
    int i2 = tid * 2;
    if (i2 + 1 < n_edges) {
        const int2 d = *reinterpret_cast<const int2*>(edge_dst + i2);
        const int2 r = *reinterpret_cast<const int2*>(g_rank + i2);
        const int2 s = *reinterpret_cast<const int2*>(edge_src + i2);
        g_sorted2[__ldg(g_start + d.x) + r.x] = make_int2(i2 + 0, s.x);
        g_sorted2[__ldg(g_start + d.y) + r.y] = make_int2(i2 + 1, s.y);
    } else if (i2 < n_edges) {
        g_sorted2[g_start[edge_dst[i2]] + g_rank[i2]] = make_int2(i2, edge_src[i2]);
    }
    if (tid < n_nodes) g_hist[tid] = 0;
}

// ---------------------------------------------------------------------------
// Fused gather + depthwise TP + bias + equivariant LN.
// TWO warps per node, split by CHANNEL GROUP (independent; no sync):
//   sub 0 (scalar path): xs,w0,w1  -> fields 0 (out0a), 2 (out1a)
//   sub 1 (vector path): xv,w2..w4 -> fields 1, 3, 4
// 3-edge unroll for max loads-in-flight; edge_weight streamed via __ldcs,
// outputs via __stcs.
// ---------------------------------------------------------------------------
__global__ void __launch_bounds__(256, 3) fused_tp_ln_kernel(
    const float* __restrict__ node_feat,   // (N, 320)
    const float* __restrict__ edge_sh,     // (E, 4)
    const float* __restrict__ edge_weight, // (E, 448)
    const float* __restrict__ tp_bias,     // (192,)
    const float* __restrict__ lnw,         // (448,)
    const float* __restrict__ lnb,         // (192,)
    float*       __restrict__ out,         // (N, 960)
    int n_nodes)
{
    const int warpInBlock = threadIdx.x >> 5;   // 0..7
    const int lane = threadIdx.x & 31;
    const int node = blockIdx.x * 4 + (warpInBlock >> 1);
    const int sub  = warpInBlock & 1;
    if (node >= n_nodes) return;

    const int beg = g_start[node];
    const int end = g_start[node + 1];
    const int deg = end - beg;
    const float fdeg = (float)deg;

    float* row = out + (size_t)node * 960u;

    if (sub == 0) {
        // ================= scalar path: out0a (4) + out1a (12) ================
        float a0 = 0.f, a1 = 0.f, a2 = 0.f, a3 = 0.f;
        float A[12];
#pragma unroll
        for (int i = 0; i < 12; i++) A[i] = 0.f;

        int ei = beg;
        for (; ei + 2 < end; ei += 3) {
            int2 es[3];
#pragma unroll
            for (int j = 0; j < 3; j++) es[j] = __ldg(g_sorted2 + ei + j);

            float4 sh[3], xs[3], w0[3], w1[3];
#pragma unroll
            for (int j = 0; j < 3; j++) {
                sh[j] = __ldg(reinterpret_cast<const float4*>(edge_sh) + es[j].x);
                xs[j] = __ldg(reinterpret_cast<const float4*>(node_feat + (size_t)es[j].y * 320u) + lane);
                const float* wr = edge_weight + (size_t)es[j].x * 448u;
                w0[j] = __ldcs(reinterpret_cast<const float4*>(wr) + lane);
                w1[j] = __ldcs(reinterpret_cast<const float4*>(wr + 128) + lane);
            }

#pragma unroll
            for (int j = 0; j < 3; j++) {
                const float ys = sh[j].x;
                a0 += w0[j].x * xs[j].x * ys; a1 += w0[j].y * xs[j].y * ys;
                a2 += w0[j].z * xs[j].z * ys; a3 += w0[j].w * xs[j].w * ys;
                const float t0 = w1[j].x * xs[j].x, t1 = w1[j].y * xs[j].y;
                const float t2 = w1[j].z * xs[j].z, t3 = w1[j].w * xs[j].w;
                A[0] += t0 * sh[j].y; A[1]  += t0 * sh[j].z; A[2]  += t0 * sh[j].w;
                A[3] += t1 * sh[j].y; A[4]  += t1 * sh[j].z; A[5]  += t1 * sh[j].w;
                A[6] += t2 * sh[j].y; A[7]  += t2 * sh[j].z; A[8]  += t2 * sh[j].w;
                A[9] += t3 * sh[j].y; A[10] += t3 * sh[j].z; A[11] += t3 * sh[j].w;
            }
        }
        for (; ei < end; ei++) {
            const int2 es0 = __ldg(g_sorted2 + ei);
            const float4 sh0 = __ldg(reinterpret_cast<const float4*>(edge_sh) + es0.x);
            const float4 xs0 = __ldg(reinterpret_cast<const float4*>(node_feat + (size_t)es0.y * 320u) + lane);
            const float* wr0 = edge_weight + (size_t)es0.x * 448u;
            const float4 w00 = __ldcs(reinterpret_cast<const float4*>(wr0) + lane);
            const float4 w10 = __ldcs(reinterpret_cast<const float4*>(wr0 + 128) + lane);
            const float ys = sh0.x;
            a0 += w00.x * xs0.x * ys; a1 += w00.y * xs0.y * ys;
            a2 += w00.z * xs0.z * ys; a3 += w00.w * xs0.w * ys;
            const float t0 = w10.x * xs0.x, t1 = w10.y * xs0.y;
            const float t2 = w10.z * xs0.z, t3 = w10.w * xs0.w;
            A[0] += t0 * sh0.y; A[1]  += t0 * sh0.z; A[2]  += t0 * sh0.w;
            A[3] += t1 * sh0.y; A[4]  += t1 * sh0.z; A[5]  += t1 * sh0.w;
            A[6] += t2 * sh0.y; A[7]  += t2 * sh0.z; A[8]  += t2 * sh0.w;
            A[9] += t3 * sh0.y; A[10] += t3 * sh0.z; A[11] += t3 * sh0.w;
        }

        const float4 b0 = __ldg(reinterpret_cast<const float4*>(tp_bias) + lane);
        a0 += fdeg * b0.x; a1 += fdeg * b0.y; a2 += fdeg * b0.z; a3 += fdeg * b0.w;

        float s0 = a0 + a1 + a2 + a3;
        float q0 = a0 * a0 + a1 * a1 + a2 * a2 + a3 * a3;
        float q2 = 0.f;
#pragma unroll
        for (int i = 0; i < 12; i++) q2 += A[i] * A[i];
        s0 = warp_sum(s0); q0 = warp_sum(q0); q2 = warp_sum(q2);

        const float mu0 = s0 * (1.f / 128.f);
        const float r0  = rsqrtf(fmaxf(q0 * (1.f / 128.f) - mu0 * mu0, 0.f) + LN_EPS);
        const float r2  = rsqrtf(q2 * (1.f / 384.f) + LN_EPS);

        {   // field0
            const float4 wv = __ldg(reinterpret_cast<const float4*>(lnw) + lane);
            const float4 bv = __ldg(reinterpret_cast<const float4*>(lnb) + lane);
            float4 o;
            o.x = (a0 - mu0) * r0 * wv.x + bv.x;
            o.y = (a1 - mu0) * r0 * wv.y + bv.y;
            o.z = (a2 - mu0) * r0 * wv.z + bv.z;
            o.w = (a3 - mu0) * r0 * wv.w + bv.w;
            __stcs(reinterpret_cast<float4*>(row + 4 * lane), o);
        }
        {   // field2: channels u = 4*lane + {0..3}
            const float4 wv = __ldg(reinterpret_cast<const float4*>(lnw + 192) + lane);
            const float sa = wv.x * r2, sb = wv.y * r2, sc = wv.z * r2, sd = wv.w * r2;
            __stcs(reinterpret_cast<float4*>(row + 192 + 12 * lane),
                   make_float4(A[0] * sa, A[1] * sa, A[2]  * sa, A[3]  * sb));
            __stcs(reinterpret_cast<float4*>(row + 192 + 12 * lane + 4),
                   make_float4(A[4] * sb, A[5] * sb, A[6]  * sc, A[7]  * sc));
            __stcs(reinterpret_cast<float4*>(row + 192 + 12 * lane + 8),
                   make_float4(A[8] * sc, A[9] * sd, A[10] * sd, A[11] * sd));
        }
    } else {
        // ============ vector path: out0b (2) + out1b (6) + out1c (6) ==========
        float ob0 = 0.f, ob1 = 0.f;
        float B[6], C[6];
#pragma unroll
        for (int i = 0; i < 6; i++) { B[i] = 0.f; C[i] = 0.f; }

        int ei = beg;
        for (; ei + 2 < end; ei += 3) {
            int2 es[3];
#pragma unroll
            for (int j = 0; j < 3; j++) es[j] = __ldg(g_sorted2 + ei + j);

            float4 sh[3];
            float2 w2[3], w3[3], w4[3], p0[3], p1[3], p2[3];
#pragma unroll
            for (int j = 0; j < 3; j++) {
                sh[j] = __ldg(reinterpret_cast<const float4*>(edge_sh) + es[j].x);
                const float* xr = node_feat + (size_t)es[j].y * 320u + 128u;
                const float* wr = edge_weight + (size_t)es[j].x * 448u;
                w2[j] = __ldcs(reinterpret_cast<const float2*>(wr + 256) + lane);
                w3[j] = __ldcs(reinterpret_cast<const float2*>(wr + 320) + lane);
                w4[j] = __ldcs(reinterpret_cast<const float2*>(wr + 384) + lane);
                p0[j] = __ldg(reinterpret_cast<const float2*>(xr + 6 * lane));
                p1[j] = __ldg(reinterpret_cast<const float2*>(xr + 6 * lane + 2));
                p2[j] = __ldg(reinterpret_cast<const float2*>(xr + 6 * lane + 4));
            }

#pragma unroll
            for (int j = 0; j < 3; j++) {
                const float ys = sh[j].x, yv0 = sh[j].y, yv1 = sh[j].z, yv2 = sh[j].w;
                const float d0 = p0[j].x * yv0 + p0[j].y * yv1 + p1[j].x * yv2;
                const float d1 = p1[j].y * yv0 + p2[j].x * yv1 + p2[j].y * yv2;
                ob0 += w3[j].x * d0 * INV_SQRT3;
                ob1 += w3[j].y * d1 * INV_SQRT3;
                const float c0 = w2[j].x * ys, c1 = w2[j].y * ys;
                B[0] += c0 * p0[j].x; B[1] += c0 * p0[j].y; B[2] += c0 * p1[j].x;
                B[3] += c1 * p1[j].y; B[4] += c1 * p2[j].x; B[5] += c1 * p2[j].y;
                const float k0 = w4[j].x * INV_SQRT2, k1 = w4[j].y * INV_SQRT2;
                C[0] += k0 * (p0[j].y * yv2 - p1[j].x * yv1);
                C[1] += k0 * (p1[j].x * yv0 - p0[j].x * yv2);
                C[2] += k0 * (p0[j].x * yv1 - p0[j].y * yv0);
                C[3] += k1 * (p2[j].x * yv2 - p2[j].y * yv1);
                C[4] += k1 * (p2[j].y * yv0 - p1[j].y * yv2);
                C[5] += k1 * (p1[j].y * yv1 - p2[j].x * yv0);
            }
        }
        for (; ei < end; ei++) {
            const int2 es0 = __ldg(g_sorted2 + ei);
            const float4 sh0 = __ldg(reinterpret_cast<const float4*>(edge_sh) + es0.x);
            const float* xr0 = node_feat + (size_t)es0.y * 320u + 128u;
            const float* wr0 = edge_weight + (size_t)es0.x * 448u;
            const float2 w20 = __ldcs(reinterpret_cast<const float2*>(wr0 + 256) + lane);
            const float2 w30 = __ldcs(reinterpret_cast<const float2*>(wr0 + 320) + lane);
            const float2 w40 = __ldcs(reinterpret_cast<const float2*>(wr0 + 384) + lane);
            const float2 p00 = __ldg(reinterpret_cast<const float2*>(xr0 + 6 * lane));
            const float2 p10 = __ldg(reinterpret_cast<const float2*>(xr0 + 6 * lane + 2));
            const float2 p20 = __ldg(reinterpret_cast<const float2*>(xr0 + 6 * lane + 4));
            const float ys = sh0.x, yv0 = sh0.y, yv1 = sh0.z, yv2 = sh0.w;
            const float d0 = p00.x * yv0 + p00.y * yv1 + p10.x * yv2;
            const float d1 = p10.y * yv0 + p20.x * yv1 + p20.y * yv2;
            ob0 += w30.x * d0 * INV_SQRT3;
            ob1 += w30.y * d1 * INV_SQRT3;
            const float c0 = w20.x * ys, c1 = w20.y * ys;
            B[0] += c0 * p00.x; B[1] += c0 * p00.y; B[2] += c0 * p10.x;
            B[3] += c1 * p10.y; B[4] += c1 * p20.x; B[5] += c1 * p20.y;
            const float k0 = w40.x * INV_SQRT2, k1 = w40.y * INV_SQRT2;
            C[0] += k0 * (p00.y * yv2 - p10.x * yv1);
            C[1] += k0 * (p10.x * yv0 - p00.x * yv2);
            C[2] += k0 * (p00.x * yv1 - p00.y * yv0);
            C[3] += k1 * (p20.x * yv2 - p20.y * yv1);
            C[4] += k1 * (p20.y * yv0 - p10.y * yv2);
            C[5] += k1 * (p10.y * yv1 - p20.x * yv0);
        }

        const float2 bb = __ldg(reinterpret_cast<const float2*>(tp_bias + 128) + lane);
        ob0 += fdeg * bb.x; ob1 += fdeg * bb.y;

        float s1 = ob0 + ob1;
        float q1 = ob0 * ob0 + ob1 * ob1;
        float q3 = 0.f, q4 = 0.f;
#pragma unroll
        for (int i = 0; i < 6; i++) { q3 += B[i] * B[i]; q4 += C[i] * C[i]; }
        s1 = warp_sum(s1); q1 = warp_sum(q1);
        q3 = warp_sum(q3); q4 = warp_sum(q4);

        const float mu1 = s1 * (1.f / 64.f);
        const float r1  = rsqrtf(fmaxf(q1 * (1.f / 64.f) - mu1 * mu1, 0.f) + LN_EPS);
        const float r3  = rsqrtf(q3 * (1.f / 192.f) + LN_EPS);
        const float r4  = rsqrtf(q4 * (1.f / 192.f) + LN_EPS);

        {   // field1
            const float2 wv = __ldg(reinterpret_cast<const float2*>(lnw + 128) + lane);
            const float2 bv = __ldg(reinterpret_cast<const float2*>(lnb + 128) + lane);
            float2 o;
            o.x = (ob0 - mu1) * r1 * wv.x + bv.x;
            o.y = (ob1 - mu1) * r1 * wv.y + bv.y;
            __stcs(reinterpret_cast<float2*>(row + 128 + 2 * lane), o);
        }
        {   // field3
            const float2 wv = __ldg(reinterpret_cast<const float2*>(lnw + 320) + lane);
            const float sa = wv.x * r3, sb = wv.y * r3;
            __stcs(reinterpret_cast<float2*>(row + 576 + 6 * lane),     make_float2(B[0] * sa, B[1] * sa));
            __stcs(reinterpret_cast<float2*>(row + 576 + 6 * lane + 2), make_float2(B[2] * sa, B[3] * sb));
            __stcs(reinterpret_cast<float2*>(row + 576 + 6 * lane + 4), make_float2(B[4] * sb, B[5] * sb));
        }
        {   // field4
            const float2 wv = __ldg(reinterpret_cast<const float2*>(lnw + 384) + lane);
            const float sa = wv.x * r4, sb = wv.y * r4;
            __stcs(reinterpret_cast<float2*>(row + 768 + 6 * lane),     make_float2(C[0] * sa, C[1] * sa));
            __stcs(reinterpret_cast<float2*>(row + 768 + 6 * lane + 2), make_float2(C[2] * sa, C[3] * sb));
            __stcs(reinterpret_cast<float2*>(row + 768 + 6 * lane + 4), make_float2(C[4] * sb, C[5] * sb));
        }
    }
}

// ---------------------------------------------------------------------------
extern "C" void kernel_launch(void* const* d_in, const int* in_sizes, int n_in,
                              void* d_out, int out_size)
{
    const float* node_feat   = (const float*)d_in[0];
    const float* edge_sh     = (const float*)d_in[1];
    const float* edge_weight = (const float*)d_in[2];
    const float* tp_bias     = (const float*)d_in[3];
    const float* ln_weight   = (const float*)d_in[4];
    const float* ln_bias     = (const float*)d_in[5];
    const int*   edge_src    = (const int*)d_in[6];
    const int*   edge_dst    = (const int*)d_in[7];
    float* out = (float*)d_out;

    const int n_nodes = in_sizes[0] / 320;
    const int n_edges = in_sizes[7];

    {
        const int threads = (n_edges + 1) / 2;
        hist_count_kernel<<<(threads + 255) / 256, 256>>>(edge_dst, n_edges);
    }
    scan_kernel<<<1, 1024>>>(n_nodes);
    {
        const int threads = (n_edges + 1) / 2;
        scatter_kernel<<<(threads + 255) / 256, 256>>>(edge_dst, edge_src,
                                                       n_edges, n_nodes);
    }

    // 2 warps per node (channel-split), 4 nodes per 256-thread block
    const int blocks = (n_nodes + 3) / 4;
    fused_tp_ln_kernel<<<blocks, 256>>>(node_feat, edge_sh, edge_weight,
                                        tp_bias, ln_weight, ln_bias,
                                        out, n_nodes);
}

// round 12
// speedup vs baseline: 1.5495x; 1.0041x over previous
#include <cuda_runtime.h>
#include <cuda_bf16.h>
#include <cstdint>

#define INV_SQRT3 0.57735026918962576451f
#define INV_SQRT2 0.70710678118654752440f
#define LN_EPS 1e-5f

#define MAX_NODES 16384
#define MAX_EDGES 131072

// scratch (allocation-free rule: __device__ globals; statically zero-initialized)
__device__ int  g_hist[MAX_NODES];          // ALWAYS zero at kernel_launch entry
__device__ int  g_rank[MAX_EDGES];
__device__ int  g_start[MAX_NODES + 1];
__device__ int2 g_sorted2[MAX_EDGES];       // (edge_id, src_node)

__device__ __forceinline__ float warp_sum(float v) {
    v += __shfl_xor_sync(0xffffffffu, v, 16);
    v += __shfl_xor_sync(0xffffffffu, v, 8);
    v += __shfl_xor_sync(0xffffffffu, v, 4);
    v += __shfl_xor_sync(0xffffffffu, v, 2);
    v += __shfl_xor_sync(0xffffffffu, v, 1);
    return v;
}

// ---------------------------------------------------------------------------
// Sort pipeline: counting sort of edge ids by edge_dst (rank-based).
// ---------------------------------------------------------------------------
__global__ void hist_count_kernel(const int* __restrict__ edge_dst, int n_edges) {
    int i2 = (blockIdx.x * blockDim.x + threadIdx.x) * 2;
    if (i2 + 1 < n_edges) {
        const int2 d = *reinterpret_cast<const int2*>(edge_dst + i2);
        g_rank[i2 + 0] = atomicAdd(&g_hist[d.x], 1);
        g_rank[i2 + 1] = atomicAdd(&g_hist[d.y], 1);
    } else if (i2 < n_edges) {
        g_rank[i2] = atomicAdd(&g_hist[edge_dst[i2]], 1);
    }
}

// single block, 1024 threads, 16 bins per thread; shuffle-based two-level scan.
// Also re-zeros g_hist (restores the entry invariant for the next call).
__global__ void __launch_bounds__(1024) scan_kernel(int n_nodes) {
    __shared__ int swarp[32];
    const int t = threadIdx.x;
    const int lane = t & 31;
    const int wid = t >> 5;
    const int base = t * 16;

    int v[16];
    if (base + 15 < n_nodes) {
#pragma unroll
        for (int c = 0; c < 4; c++) {
            const int4 h = *reinterpret_cast<const int4*>(g_hist + base + 4 * c);
            v[4 * c + 0] = h.x; v[4 * c + 1] = h.y;
            v[4 * c + 2] = h.z; v[4 * c + 3] = h.w;
        }
        // restore invariant: g_hist == 0 at next call's entry
        const int4 z = make_int4(0, 0, 0, 0);
#pragma unroll
        for (int c = 0; c < 4; c++)
            *reinterpret_cast<int4*>(g_hist + base + 4 * c) = z;
    } else {
#pragma unroll
        for (int i = 0; i < 16; i++) {
            int idx = base + i;
            v[i] = (idx < n_nodes) ? g_hist[idx] : 0;
            if (idx < n_nodes) g_hist[idx] = 0;
        }
    }
    int s = 0;
#pragma unroll
    for (int i = 0; i < 16; i++) s += v[i];

    int inc = s;
#pragma unroll
    for (int off = 1; off < 32; off <<= 1) {
        int x = __shfl_up_sync(0xffffffffu, inc, off);
        if (lane >= off) inc += x;
    }
    if (lane == 31) swarp[wid] = inc;
    __syncthreads();

    if (wid == 0) {
        int w = swarp[lane];
        int winc = w;
#pragma unroll
        for (int off = 1; off < 32; off <<= 1) {
            int x = __shfl_up_sync(0xffffffffu, winc, off);
            if (lane >= off) winc += x;
        }
        swarp[lane] = winc - w;
    }
    __syncthreads();

    int run = swarp[wid] + (inc - s);
    int pfx[16];
#pragma unroll
    for (int i = 0; i < 16; i++) { pfx[i] = run; run += v[i]; }

    if (base + 15 < n_nodes) {
#pragma unroll
        for (int c = 0; c < 4; c++) {
            *reinterpret_cast<int4*>(g_start + base + 4 * c) =
                make_int4(pfx[4 * c + 0], pfx[4 * c + 1], pfx[4 * c + 2], pfx[4 * c + 3]);
        }
    } else {
#pragma unroll
        for (int i = 0; i < 16; i++) {
            int idx = base + i;
            if (idx < n_nodes) g_start[idx] = pfx[i];
        }
    }
    if (t == 1023) g_start[n_nodes] = run;
}

__global__ void scatter_kernel(const int* __restrict__ edge_dst,
                               const int* __restrict__ edge_src,
                               int n_edges) {
    const int tid = blockIdx.x * blockDim.x + threadIdx.x;
    int i2 = tid * 2;
    if (i2 + 1 < n_edges) {
        const int2 d = *reinterpret_cast<const int2*>(edge_dst + i2);
        const int2 r = *reinterpret_cast<const int2*>(g_rank + i2);
        const int2 s = *reinterpret_cast<const int2*>(edge_src + i2);
        g_sorted2[__ldg(g_start + d.x) + r.x] = make_int2(i2 + 0, s.x);
        g_sorted2[__ldg(g_start + d.y) + r.y] = make_int2(i2 + 1, s.y);
    } else if (i2 < n_edges) {
        g_sorted2[g_start[edge_dst[i2]] + g_rank[i2]] = make_int2(i2, edge_src[i2]);
    }
}

// ---------------------------------------------------------------------------
// Fused gather + depthwise TP + bias + equivariant LN.
// TWO warps per node, split by CHANNEL GROUP (independent; no sync):
//   sub 0 (scalar path): xs,w0,w1  -> fields 0 (out0a), 2 (out1a)
//   sub 1 (vector path): xv,w2..w4 -> fields 1, 3, 4
// 2-edge unroll with a 64-reg cap -> 4 blocks/SM (32 warps/SM).
// edge_weight streamed via __ldcs, outputs via __stcs.
// ---------------------------------------------------------------------------
__global__ void __launch_bounds__(256, 4) fused_tp_ln_kernel(
    const float* __restrict__ node_feat,   // (N, 320)
    const float* __restrict__ edge_sh,     // (E, 4)
    const float* __restrict__ edge_weight, // (E, 448)
    const float* __restrict__ tp_bias,     // (192,)
    const float* __restrict__ lnw,         // (448,)
    const float* __restrict__ lnb,         // (192,)
    float*       __restrict__ out,         // (N, 960)
    int n_nodes)
{
    const int warpInBlock = threadIdx.x >> 5;   // 0..7
    const int lane = threadIdx.x & 31;
    const int node = blockIdx.x * 4 + (warpInBlock >> 1);
    const int sub  = warpInBlock & 1;
    if (node >= n_nodes) return;

    const int beg = g_start[node];
    const int end = g_start[node + 1];
    const int deg = end - beg;
    const float fdeg = (float)deg;

    float* row = out + (size_t)node * 960u;

    if (sub == 0) {
        // ================= scalar path: out0a (4) + out1a (12) ================
        float a0 = 0.f, a1 = 0.f, a2 = 0.f, a3 = 0.f;
        float A[12];
#pragma unroll
        for (int i = 0; i < 12; i++) A[i] = 0.f;

        int ei = beg;
        for (; ei + 1 < end; ei += 2) {
            const int2 es0 = __ldg(g_sorted2 + ei);
            const int2 es1 = __ldg(g_sorted2 + ei + 1);

            const float4 sh0 = __ldg(reinterpret_cast<const float4*>(edge_sh) + es0.x);
            const float4 sh1 = __ldg(reinterpret_cast<const float4*>(edge_sh) + es1.x);
            const float4 xs0 = __ldg(reinterpret_cast<const float4*>(node_feat + (size_t)es0.y * 320u) + lane);
            const float4 xs1 = __ldg(reinterpret_cast<const float4*>(node_feat + (size_t)es1.y * 320u) + lane);
            const float* wr0 = edge_weight + (size_t)es0.x * 448u;
            const float* wr1 = edge_weight + (size_t)es1.x * 448u;
            const float4 w00 = __ldcs(reinterpret_cast<const float4*>(wr0) + lane);
            const float4 w01 = __ldcs(reinterpret_cast<const float4*>(wr1) + lane);
            const float4 w10 = __ldcs(reinterpret_cast<const float4*>(wr0 + 128) + lane);
            const float4 w11 = __ldcs(reinterpret_cast<const float4*>(wr1 + 128) + lane);

            {
                const float ys = sh0.x;
                a0 += w00.x * xs0.x * ys; a1 += w00.y * xs0.y * ys;
                a2 += w00.z * xs0.z * ys; a3 += w00.w * xs0.w * ys;
                const float t0 = w10.x * xs0.x, t1 = w10.y * xs0.y;
                const float t2 = w10.z * xs0.z, t3 = w10.w * xs0.w;
                A[0] += t0 * sh0.y; A[1]  += t0 * sh0.z; A[2]  += t0 * sh0.w;
                A[3] += t1 * sh0.y; A[4]  += t1 * sh0.z; A[5]  += t1 * sh0.w;
                A[6] += t2 * sh0.y; A[7]  += t2 * sh0.z; A[8]  += t2 * sh0.w;
                A[9] += t3 * sh0.y; A[10] += t3 * sh0.z; A[11] += t3 * sh0.w;
            }
            {
                const float ys = sh1.x;
                a0 += w01.x * xs1.x * ys; a1 += w01.y * xs1.y * ys;
                a2 += w01.z * xs1.z * ys; a3 += w01.w * xs1.w * ys;
                const float t0 = w11.x * xs1.x, t1 = w11.y * xs1.y;
                const float t2 = w11.z * xs1.z, t3 = w11.w * xs1.w;
                A[0] += t0 * sh1.y; A[1]  += t0 * sh1.z; A[2]  += t0 * sh1.w;
                A[3] += t1 * sh1.y; A[4]  += t1 * sh1.z; A[5]  += t1 * sh1.w;
                A[6] += t2 * sh1.y; A[7]  += t2 * sh1.z; A[8]  += t2 * sh1.w;
                A[9] += t3 * sh1.y; A[10] += t3 * sh1.z; A[11] += t3 * sh1.w;
            }
        }
        if (ei < end) {
            const int2 es0 = __ldg(g_sorted2 + ei);
            const float4 sh0 = __ldg(reinterpret_cast<const float4*>(edge_sh) + es0.x);
            const float4 xs0 = __ldg(reinterpret_cast<const float4*>(node_feat + (size_t)es0.y * 320u) + lane);
            const float* wr0 = edge_weight + (size_t)es0.x * 448u;
            const float4 w00 = __ldcs(reinterpret_cast<const float4*>(wr0) + lane);
            const float4 w10 = __ldcs(reinterpret_cast<const float4*>(wr0 + 128) + lane);
            const float ys = sh0.x;
            a0 += w00.x * xs0.x * ys; a1 += w00.y * xs0.y * ys;
            a2 += w00.z * xs0.z * ys; a3 += w00.w * xs0.w * ys;
            const float t0 = w10.x * xs0.x, t1 = w10.y * xs0.y;
            const float t2 = w10.z * xs0.z, t3 = w10.w * xs0.w;
            A[0] += t0 * sh0.y; A[1]  += t0 * sh0.z; A[2]  += t0 * sh0.w;
            A[3] += t1 * sh0.y; A[4]  += t1 * sh0.z; A[5]  += t1 * sh0.w;
            A[6] += t2 * sh0.y; A[7]  += t2 * sh0.z; A[8]  += t2 * sh0.w;
            A[9] += t3 * sh0.y; A[10] += t3 * sh0.z; A[11] += t3 * sh0.w;
        }

        const float4 b0 = __ldg(reinterpret_cast<const float4*>(tp_bias) + lane);
        a0 += fdeg * b0.x; a1 += fdeg * b0.y; a2 += fdeg * b0.z; a3 += fdeg * b0.w;

        float s0 = a0 + a1 + a2 + a3;
        float q0 = a0 * a0 + a1 * a1 + a2 * a2 + a3 * a3;
        float q2 = 0.f;
#pragma unroll
        for (int i = 0; i < 12; i++) q2 += A[i] * A[i];
        s0 = warp_sum(s0); q0 = warp_sum(q0); q2 = warp_sum(q2);

        const float mu0 = s0 * (1.f / 128.f);
        const float r0  = rsqrtf(fmaxf(q0 * (1.f / 128.f) - mu0 * mu0, 0.f) + LN_EPS);
        const float r2  = rsqrtf(q2 * (1.f / 384.f) + LN_EPS);

        {   // field0
            const float4 wv = __ldg(reinterpret_cast<const float4*>(lnw) + lane);
            const float4 bv = __ldg(reinterpret_cast<const float4*>(lnb) + lane);
            float4 o;
            o.x = (a0 - mu0) * r0 * wv.x + bv.x;
            o.y = (a1 - mu0) * r0 * wv.y + bv.y;
            o.z = (a2 - mu0) * r0 * wv.z + bv.z;
            o.w = (a3 - mu0) * r0 * wv.w + bv.w;
            __stcs(reinterpret_cast<float4*>(row + 4 * lane), o);
        }
        {   // field2: channels u = 4*lane + {0..3}
            const float4 wv = __ldg(reinterpret_cast<const float4*>(lnw + 192) + lane);
            const float sa = wv.x * r2, sb = wv.y * r2, sc = wv.z * r2, sd = wv.w * r2;
            __stcs(reinterpret_cast<float4*>(row + 192 + 12 * lane),
                   make_float4(A[0] * sa, A[1] * sa, A[2]  * sa, A[3]  * sb));
            __stcs(reinterpret_cast<float4*>(row + 192 + 12 * lane + 4),
                   make_float4(A[4] * sb, A[5] * sb, A[6]  * sc, A[7]  * sc));
            __stcs(reinterpret_cast<float4*>(row + 192 + 12 * lane + 8),
                   make_float4(A[8] * sc, A[9] * sd, A[10] * sd, A[11] * sd));
        }
    } else {
        // ============ vector path: out0b (2) + out1b (6) + out1c (6) ==========
        float ob0 = 0.f, ob1 = 0.f;
        float B[6], C[6];
#pragma unroll
        for (int i = 0; i < 6; i++) { B[i] = 0.f; C[i] = 0.f; }

        int ei = beg;
        for (; ei + 1 < end; ei += 2) {
            const int2 es0 = __ldg(g_sorted2 + ei);
            const int2 es1 = __ldg(g_sorted2 + ei + 1);

            const float4 sh0 = __ldg(reinterpret_cast<const float4*>(edge_sh) + es0.x);
            const float4 sh1 = __ldg(reinterpret_cast<const float4*>(edge_sh) + es1.x);
            const float* xr0 = node_feat + (size_t)es0.y * 320u + 128u;
            const float* xr1 = node_feat + (size_t)es1.y * 320u + 128u;
            const float* wr0 = edge_weight + (size_t)es0.x * 448u;
            const float* wr1 = edge_weight + (size_t)es1.x * 448u;

            const float2 w20 = __ldcs(reinterpret_cast<const float2*>(wr0 + 256) + lane);
            const float2 w30 = __ldcs(reinterpret_cast<const float2*>(wr0 + 320) + lane);
            const float2 w40 = __ldcs(reinterpret_cast<const float2*>(wr0 + 384) + lane);
            const float2 p00 = __ldg(reinterpret_cast<const float2*>(xr0 + 6 * lane));
            const float2 p10 = __ldg(reinterpret_cast<const float2*>(xr0 + 6 * lane + 2));
            const float2 p20 = __ldg(reinterpret_cast<const float2*>(xr0 + 6 * lane + 4));

            const float2 w21 = __ldcs(reinterpret_cast<const float2*>(wr1 + 256) + lane);
            const float2 w31 = __ldcs(reinterpret_cast<const float2*>(wr1 + 320) + lane);
            const float2 w41 = __ldcs(reinterpret_cast<const float2*>(wr1 + 384) + lane);
            const float2 p01 = __ldg(reinterpret_cast<const float2*>(xr1 + 6 * lane));
            const float2 p11 = __ldg(reinterpret_cast<const float2*>(xr1 + 6 * lane + 2));
            const float2 p21 = __ldg(reinterpret_cast<const float2*>(xr1 + 6 * lane + 4));

            {
                const float ys = sh0.x, yv0 = sh0.y, yv1 = sh0.z, yv2 = sh0.w;
                const float d0 = p00.x * yv0 + p00.y * yv1 + p10.x * yv2;
                const float d1 = p10.y * yv0 + p20.x * yv1 + p20.y * yv2;
                ob0 += w30.x * d0 * INV_SQRT3;
                ob1 += w30.y * d1 * INV_SQRT3;
                const float c0 = w20.x * ys, c1 = w20.y * ys;
                B[0] += c0 * p00.x; B[1] += c0 * p00.y; B[2] += c0 * p10.x;
                B[3] += c1 * p10.y; B[4] += c1 * p20.x; B[5] += c1 * p20.y;
                const float k0 = w40.x * INV_SQRT2, k1 = w40.y * INV_SQRT2;
                C[0] += k0 * (p00.y * yv2 - p10.x * yv1);
                C[1] += k0 * (p10.x * yv0 - p00.x * yv2);
                C[2] += k0 * (p00.x * yv1 - p00.y * yv0);
                C[3] += k1 * (p20.x * yv2 - p20.y * yv1);
                C[4] += k1 * (p20.y * yv0 - p10.y * yv2);
                C[5] += k1 * (p10.y * yv1 - p20.x * yv0);
            }
            {
                const float ys = sh1.x, yv0 = sh1.y, yv1 = sh1.z, yv2 = sh1.w;
                const float d0 = p01.x * yv0 + p01.y * yv1 + p11.x * yv2;
                const float d1 = p11.y * yv0 + p21.x * yv1 + p21.y * yv2;
                ob0 += w31.x * d0 * INV_SQRT3;
                ob1 += w31.y * d1 * INV_SQRT3;
                const float c0 = w21.x * ys, c1 = w21.y * ys;
                B[0] += c0 * p01.x; B[1] += c0 * p01.y; B[2] += c0 * p11.x;
                B[3] += c1 * p11.y; B[4] += c1 * p21.x; B[5] += c1 * p21.y;
                const float k0 = w41.x * INV_SQRT2, k1 = w41.y * INV_SQRT2;
                C[0] += k0 * (p01.y * yv2 - p11.x * yv1);
                C[1] += k0 * (p11.x * yv0 - p01.x * yv2);
                C[2] += k0 * (p01.x * yv1 - p01.y * yv0);
                C[3] += k1 * (p21.x * yv2 - p21.y * yv1);
                C[4] += k1 * (p21.y * yv0 - p11.y * yv2);
                C[5] += k1 * (p11.y * yv1 - p21.x * yv0);
            }
        }
        if (ei < end) {
            const int2 es0 = __ldg(g_sorted2 + ei);
            const float4 sh0 = __ldg(reinterpret_cast<const float4*>(edge_sh) + es0.x);
            const float* xr0 = node_feat + (size_t)es0.y * 320u + 128u;
            const float* wr0 = edge_weight + (size_t)es0.x * 448u;
            const float2 w20 = __ldcs(reinterpret_cast<const float2*>(wr0 + 256) + lane);
            const float2 w30 = __ldcs(reinterpret_cast<const float2*>(wr0 + 320) + lane);
            const float2 w40 = __ldcs(reinterpret_cast<const float2*>(wr0 + 384) + lane);
            const float2 p00 = __ldg(reinterpret_cast<const float2*>(xr0 + 6 * lane));
            const float2 p10 = __ldg(reinterpret_cast<const float2*>(xr0 + 6 * lane + 2));
            const float2 p20 = __ldg(reinterpret_cast<const float2*>(xr0 + 6 * lane + 4));
            const float ys = sh0.x, yv0 = sh0.y, yv1 = sh0.z, yv2 = sh0.w;
            const float d0 = p00.x * yv0 + p00.y * yv1 + p10.x * yv2;
            const float d1 = p10.y * yv0 + p20.x * yv1 + p20.y * yv2;
            ob0 += w30.x * d0 * INV_SQRT3;
            ob1 += w30.y * d1 * INV_SQRT3;
            const float c0 = w20.x * ys, c1 = w20.y * ys;
            B[0] += c0 * p00.x; B[1] += c0 * p00.y; B[2] += c0 * p10.x;
            B[3] += c1 * p10.y; B[4] += c1 * p20.x; B[5] += c1 * p20.y;
            const float k0 = w40.x * INV_SQRT2, k1 = w40.y * INV_SQRT2;
            C[0] += k0 * (p00.y * yv2 - p10.x * yv1);
            C[1] += k0 * (p10.x * yv0 - p00.x * yv2);
            C[2] += k0 * (p00.x * yv1 - p00.y * yv0);
            C[3] += k1 * (p20.x * yv2 - p20.y * yv1);
            C[4] += k1 * (p20.y * yv0 - p10.y * yv2);
            C[5] += k1 * (p10.y * yv1 - p20.x * yv0);
        }

        const float2 bb = __ldg(reinterpret_cast<const float2*>(tp_bias + 128) + lane);
        ob0 += fdeg * bb.x; ob1 += fdeg * bb.y;

        float s1 = ob0 + ob1;
        float q1 = ob0 * ob0 + ob1 * ob1;
        float q3 = 0.f, q4 = 0.f;
#pragma unroll
        for (int i = 0; i < 6; i++) { q3 += B[i] * B[i]; q4 += C[i] * C[i]; }
        s1 = warp_sum(s1); q1 = warp_sum(q1);
        q3 = warp_sum(q3); q4 = warp_sum(q4);

        const float mu1 = s1 * (1.f / 64.f);
        const float r1  = rsqrtf(fmaxf(q1 * (1.f / 64.f) - mu1 * mu1, 0.f) + LN_EPS);
        const float r3  = rsqrtf(q3 * (1.f / 192.f) + LN_EPS);
        const float r4  = rsqrtf(q4 * (1.f / 192.f) + LN_EPS);

        {   // field1
            const float2 wv = __ldg(reinterpret_cast<const float2*>(lnw + 128) + lane);
            const float2 bv = __ldg(reinterpret_cast<const float2*>(lnb + 128) + lane);
            float2 o;
            o.x = (ob0 - mu1) * r1 * wv.x + bv.x;
            o.y = (ob1 - mu1) * r1 * wv.y + bv.y;
            __stcs(reinterpret_cast<float2*>(row + 128 + 2 * lane), o);
        }
        {   // field3
            const float2 wv = __ldg(reinterpret_cast<const float2*>(lnw + 320) + lane);
            const float sa = wv.x * r3, sb = wv.y * r3;
            __stcs(reinterpret_cast<float2*>(row + 576 + 6 * lane),     make_float2(B[0] * sa, B[1] * sa));
            __stcs(reinterpret_cast<float2*>(row + 576 + 6 * lane + 2), make_float2(B[2] * sa, B[3] * sb));
            __stcs(reinterpret_cast<float2*>(row + 576 + 6 * lane + 4), make_float2(B[4] * sb, B[5] * sb));
        }
        {   // field4
            const float2 wv = __ldg(reinterpret_cast<const float2*>(lnw + 384) + lane);
            const float sa = wv.x * r4, sb = wv.y * r4;
            __stcs(reinterpret_cast<float2*>(row + 768 + 6 * lane),     make_float2(C[0] * sa, C[1] * sa));
            __stcs(reinterpret_cast<float2*>(row + 768 + 6 * lane + 2), make_float2(C[2] * sa, C[3] * sb));
            __stcs(reinterpret_cast<float2*>(row + 768 + 6 * lane + 4), make_float2(C[4] * sb, C[5] * sb));
        }
    }
}

// ---------------------------------------------------------------------------
extern "C" void kernel_launch(void* const* d_in, const int* in_sizes, int n_in,
                              void* d_out, int out_size)
{
    const float* node_feat   = (const float*)d_in[0];
    const float* edge_sh     = (const float*)d_in[1];
    const float* edge_weight = (const float*)d_in[2];
    const float* tp_bias     = (const float*)d_in[3];
    const float* ln_weight   = (const float*)d_in[4];
    const float* ln_bias     = (const float*)d_in[5];
    const int*   edge_src    = (const int*)d_in[6];
    const int*   edge_dst    = (const int*)d_in[7];
    float* out = (float*)d_out;

    const int n_nodes = in_sizes[0] / 320;
    const int n_edges = in_sizes[7];

    {
        const int threads = (n_edges + 1) / 2;
        hist_count_kernel<<<(threads + 255) / 256, 256>>>(edge_dst, n_edges);
    }
    scan_kernel<<<1, 1024>>>(n_nodes);
    {
        const int threads = (n_edges + 1) / 2;
        scatter_kernel<<<(threads + 255) / 256, 256>>>(edge_dst, edge_src, n_edges);
    }

    // 2 warps per node (channel-split), 4 nodes per 256-thread block
    const int blocks = (n_nodes + 3) / 4;
    fused_tp_ln_kernel<<<blocks, 256>>>(node_feat, edge_sh, edge_weight,
                                        tp_bias, ln_weight, ln_bias,
                                        out, n_nodes);
}